// round 3
// baseline (speedup 1.0000x reference)
#include <cuda_runtime.h>
#include <math.h>

// Problem constants
#define BB 4
#define NN 2048
#define CC 1024
#define HH 16
#define DD 64
#define FFD 4096
#define MROWS (BB * NN)   // 8192

// -------------------- scratch (allocation-free: __device__ globals) ---------
__device__ float g_h[MROWS * CC];        // LN output (reused for LN1 and LN2)
__device__ float g_qkv[MROWS * 3 * CC];  // qkv projection
__device__ float g_attn[MROWS * CC];     // attention output (pre-proj)
__device__ float g_x1[MROWS * CC];       // x + attn_proj
__device__ float g_g1[MROWS * FFD];      // h @ w1^T, then gated product
__device__ float g_g3[MROWS * FFD];      // h @ w3^T

// ============================================================================
// LayerNorm: one row (C=1024) per block, 256 threads, 1 float4/thread.
// ============================================================================
__global__ __launch_bounds__(256) void ln_kernel(
    const float* __restrict__ x, const float* __restrict__ g,
    const float* __restrict__ bta, float* __restrict__ out)
{
    __shared__ float ssum[8], ssq[8];
    const int row = blockIdx.x;
    const int tid = threadIdx.x;

    const float4 v = *(const float4*)(x + (size_t)row * CC + tid * 4);
    float s = v.x + v.y + v.z + v.w;
    float q = v.x * v.x + v.y * v.y + v.z * v.z + v.w * v.w;

    #pragma unroll
    for (int off = 16; off; off >>= 1) {
        s += __shfl_xor_sync(0xffffffffu, s, off);
        q += __shfl_xor_sync(0xffffffffu, q, off);
    }
    if ((tid & 31) == 0) { ssum[tid >> 5] = s; ssq[tid >> 5] = q; }
    __syncthreads();

    float ts = 0.f, tq = 0.f;
    #pragma unroll
    for (int i = 0; i < 8; i++) { ts += ssum[i]; tq += ssq[i]; }

    const float mean = ts * (1.f / (float)CC);
    const float var  = tq * (1.f / (float)CC) - mean * mean;
    const float r    = rsqrtf(var + 1e-6f);

    const float4 gg = *(const float4*)(g + tid * 4);
    const float4 bb = *(const float4*)(bta + tid * 4);
    float4 o;
    o.x = (v.x - mean) * r * gg.x + bb.x;
    o.y = (v.y - mean) * r * gg.y + bb.y;
    o.z = (v.z - mean) * r * gg.z + bb.z;
    o.w = (v.w - mean) * r * gg.w + bb.w;
    *(float4*)(out + (size_t)row * CC + tid * 4) = o;
}

// ============================================================================
// SGEMM (NT): C[M,N] = A[M,K] @ B[N,K]^T (+ bias[N]) (+ res[M,N])
// A, B row-major with K contiguous. 128x128x16 tile, 256 thr, 8x8/thread.
// ============================================================================
__global__ __launch_bounds__(256, 2) void gemm_nt_kernel(
    const float* __restrict__ A, const float* __restrict__ B,
    const float* __restrict__ bias, const float* __restrict__ res,
    float* __restrict__ C, int M, int N, int K)
{
    __shared__ float As[16][128];
    __shared__ float Bs[16][128];

    const int tid = threadIdx.x;
    const int tx = tid & 15, ty = tid >> 4;
    const int m0 = blockIdx.y * 128, n0 = blockIdx.x * 128;

    const float* Ab = A + (size_t)m0 * K;
    const float* Bb = B + (size_t)n0 * K;

    float acc[8][8];
    #pragma unroll
    for (int i = 0; i < 8; i++)
        #pragma unroll
        for (int j = 0; j < 8; j++) acc[i][j] = 0.f;

    for (int k0 = 0; k0 < K; k0 += 16) {
        #pragma unroll
        for (int l = 0; l < 2; l++) {
            int f = tid + l * 256;
            int r = f >> 2, c = (f & 3) << 2;
            float4 a = *(const float4*)(Ab + (size_t)r * K + k0 + c);
            As[c + 0][r] = a.x; As[c + 1][r] = a.y;
            As[c + 2][r] = a.z; As[c + 3][r] = a.w;
            float4 b = *(const float4*)(Bb + (size_t)r * K + k0 + c);
            Bs[c + 0][r] = b.x; Bs[c + 1][r] = b.y;
            Bs[c + 2][r] = b.z; Bs[c + 3][r] = b.w;
        }
        __syncthreads();

        #pragma unroll
        for (int kk = 0; kk < 16; kk++) {
            float af[8], bf[8];
            *(float4*)&af[0] = *(const float4*)&As[kk][ty * 8];
            *(float4*)&af[4] = *(const float4*)&As[kk][ty * 8 + 4];
            *(float4*)&bf[0] = *(const float4*)&Bs[kk][tx * 8];
            *(float4*)&bf[4] = *(const float4*)&Bs[kk][tx * 8 + 4];
            #pragma unroll
            for (int i = 0; i < 8; i++)
                #pragma unroll
                for (int j = 0; j < 8; j++)
                    acc[i][j] += af[i] * bf[j];
        }
        __syncthreads();
    }

    // epilogue
    float bcol[8];
    if (bias) {
        *(float4*)&bcol[0] = *(const float4*)(bias + n0 + tx * 8);
        *(float4*)&bcol[4] = *(const float4*)(bias + n0 + tx * 8 + 4);
    } else {
        #pragma unroll
        for (int j = 0; j < 8; j++) bcol[j] = 0.f;
    }

    #pragma unroll
    for (int i = 0; i < 8; i++) {
        const int row = m0 + ty * 8 + i;
        #pragma unroll
        for (int j = 0; j < 8; j += 4) {
            const int col = n0 + tx * 8 + j;
            float4 v = make_float4(acc[i][j] + bcol[j],
                                   acc[i][j + 1] + bcol[j + 1],
                                   acc[i][j + 2] + bcol[j + 2],
                                   acc[i][j + 3] + bcol[j + 3]);
            if (res) {
                float4 rr = *(const float4*)(res + (size_t)row * N + col);
                v.x += rr.x; v.y += rr.y; v.z += rr.z; v.w += rr.w;
            }
            *(float4*)(C + (size_t)row * N + col) = v;
        }
    }
}

// ============================================================================
// Flash attention (causal), fp32. Br=Bc=64, D=64. 256 threads, 4x4 thread tile.
// qkv layout: [B*N, 3C]; q at col h*64, k at 1024+h*64, v at 2048+h*64.
// Dynamic smem: Qs[64][68] | KT[64][68] (reused for P) | Vs[64][68]
// ============================================================================
#define ATT_STR 68
#define ATT_SMEM (3 * 64 * ATT_STR * 4)

__global__ __launch_bounds__(256) void attn_kernel(
    const float* __restrict__ qkv, float* __restrict__ out)
{
    extern __shared__ float sm[];
    float* Qs = sm;                       // [64][68], pre-scaled by 1/8
    float* KT = sm + 64 * ATT_STR;        // [d][c], reused as P[r][k]
    float* Vs = sm + 2 * 64 * ATT_STR;    // [c][d]

    const int tid = threadIdx.x;
    const int tx = tid & 15, ty = tid >> 4;
    const int qb = blockIdx.x;           // query block 0..31
    const int bh = blockIdx.y;           // 0..63
    const int b = bh >> 4, h = bh & 15;
    const int i0 = qb << 6;
    const size_t base = (size_t)b * NN * (3 * CC) + h * DD;

    // load Q (scaled)
    #pragma unroll
    for (int l = 0; l < 4; l++) {
        int f = tid + l * 256;
        int r = f >> 4, c = (f & 15) << 2;
        float4 v = *(const float4*)(qkv + base + (size_t)(i0 + r) * (3 * CC) + c);
        v.x *= 0.125f; v.y *= 0.125f; v.z *= 0.125f; v.w *= 0.125f;
        *(float4*)&Qs[r * ATT_STR + c] = v;
    }

    float mrow[4], lrow[4], o[4][4];
    #pragma unroll
    for (int i = 0; i < 4; i++) {
        mrow[i] = -1e30f; lrow[i] = 0.f;
        #pragma unroll
        for (int j = 0; j < 4; j++) o[i][j] = 0.f;
    }

    for (int kb = 0; kb <= qb; kb++) {
        const int k0 = kb << 6;
        __syncthreads();  // previous iter's KT/Vs reads done (also covers Q load 1st iter w/ next sync)
        #pragma unroll
        for (int l = 0; l < 4; l++) {
            int f = tid + l * 256;
            int c = f >> 4, d = (f & 15) << 2;
            float4 kv = *(const float4*)(qkv + base + CC + (size_t)(k0 + c) * (3 * CC) + d);
            KT[(d + 0) * ATT_STR + c] = kv.x;
            KT[(d + 1) * ATT_STR + c] = kv.y;
            KT[(d + 2) * ATT_STR + c] = kv.z;
            KT[(d + 3) * ATT_STR + c] = kv.w;
            float4 vv = *(const float4*)(qkv + base + 2 * CC + (size_t)(k0 + c) * (3 * CC) + d);
            *(float4*)&Vs[c * ATT_STR + d] = vv;
        }
        __syncthreads();

        // S = Q K^T (scaled)
        float s[4][4];
        #pragma unroll
        for (int i = 0; i < 4; i++)
            #pragma unroll
            for (int j = 0; j < 4; j++) s[i][j] = 0.f;

        #pragma unroll 16
        for (int d = 0; d < 64; d++) {
            float4 kf = *(const float4*)&KT[d * ATT_STR + (tx << 2)];
            float q0 = Qs[(ty * 4 + 0) * ATT_STR + d];
            float q1 = Qs[(ty * 4 + 1) * ATT_STR + d];
            float q2 = Qs[(ty * 4 + 2) * ATT_STR + d];
            float q3 = Qs[(ty * 4 + 3) * ATT_STR + d];
            s[0][0] += q0 * kf.x; s[0][1] += q0 * kf.y; s[0][2] += q0 * kf.z; s[0][3] += q0 * kf.w;
            s[1][0] += q1 * kf.x; s[1][1] += q1 * kf.y; s[1][2] += q1 * kf.z; s[1][3] += q1 * kf.w;
            s[2][0] += q2 * kf.x; s[2][1] += q2 * kf.y; s[2][2] += q2 * kf.z; s[2][3] += q2 * kf.w;
            s[3][0] += q3 * kf.x; s[3][1] += q3 * kf.y; s[3][2] += q3 * kf.z; s[3][3] += q3 * kf.w;
        }

        // causal mask on diagonal block
        if (kb == qb) {
            #pragma unroll
            for (int i = 0; i < 4; i++)
                #pragma unroll
                for (int j = 0; j < 4; j++)
                    if (k0 + (tx << 2) + j > i0 + (ty << 2) + i) s[i][j] = -1e30f;
        }

        // online softmax per owned row (reduction across the 16 tx lanes)
        #pragma unroll
        for (int i = 0; i < 4; i++) {
            float mx = fmaxf(fmaxf(s[i][0], s[i][1]), fmaxf(s[i][2], s[i][3]));
            #pragma unroll
            for (int off = 8; off; off >>= 1)
                mx = fmaxf(mx, __shfl_xor_sync(0xffffffffu, mx, off));
            const float mn = fmaxf(mrow[i], mx);
            const float alpha = __expf(mrow[i] - mn);
            mrow[i] = mn;
            float rs = 0.f;
            #pragma unroll
            for (int j = 0; j < 4; j++) { s[i][j] = __expf(s[i][j] - mn); rs += s[i][j]; }
            #pragma unroll
            for (int off = 8; off; off >>= 1)
                rs += __shfl_xor_sync(0xffffffffu, rs, off);
            lrow[i] = lrow[i] * alpha + rs;
            o[i][0] *= alpha; o[i][1] *= alpha; o[i][2] *= alpha; o[i][3] *= alpha;
        }

        __syncthreads();  // all KT reads done before overwriting with P
        #pragma unroll
        for (int i = 0; i < 4; i++) {
            float4 pv = make_float4(s[i][0], s[i][1], s[i][2], s[i][3]);
            *(float4*)&KT[(ty * 4 + i) * ATT_STR + (tx << 2)] = pv;
        }
        __syncthreads();

        // O += P @ V
        #pragma unroll 16
        for (int k = 0; k < 64; k++) {
            float4 vf = *(const float4*)&Vs[k * ATT_STR + (tx << 2)];
            float p0 = KT[(ty * 4 + 0) * ATT_STR + k];
            float p1 = KT[(ty * 4 + 1) * ATT_STR + k];
            float p2 = KT[(ty * 4 + 2) * ATT_STR + k];
            float p3 = KT[(ty * 4 + 3) * ATT_STR + k];
            o[0][0] += p0 * vf.x; o[0][1] += p0 * vf.y; o[0][2] += p0 * vf.z; o[0][3] += p0 * vf.w;
            o[1][0] += p1 * vf.x; o[1][1] += p1 * vf.y; o[1][2] += p1 * vf.z; o[1][3] += p1 * vf.w;
            o[2][0] += p2 * vf.x; o[2][1] += p2 * vf.y; o[2][2] += p2 * vf.z; o[2][3] += p2 * vf.w;
            o[3][0] += p3 * vf.x; o[3][1] += p3 * vf.y; o[3][2] += p3 * vf.z; o[3][3] += p3 * vf.w;
        }
    }

    #pragma unroll
    for (int i = 0; i < 4; i++) {
        const float inv = 1.f / lrow[i];
        float4 ov = make_float4(o[i][0] * inv, o[i][1] * inv, o[i][2] * inv, o[i][3] * inv);
        *(float4*)(out + (size_t)(b * NN + i0 + ty * 4 + i) * CC + h * DD + (tx << 2)) = ov;
    }
}

// ============================================================================
// SwiGLU gate: a = silu(a) * c, in place over a.
// ============================================================================
__global__ __launch_bounds__(256) void glu_kernel(
    float* __restrict__ a, const float* __restrict__ c)
{
    const size_t i = ((size_t)blockIdx.x * 256 + threadIdx.x) * 4;
    float4 v = *(const float4*)(a + i);
    float4 g = *(const float4*)(c + i);
    v.x = v.x * g.x / (1.f + __expf(-v.x));
    v.y = v.y * g.y / (1.f + __expf(-v.y));
    v.z = v.z * g.z / (1.f + __expf(-v.z));
    v.w = v.w * g.w / (1.f + __expf(-v.w));
    *(float4*)(a + i) = v;
}

// ============================================================================
// Launch
// ============================================================================
extern "C" void kernel_launch(void* const* d_in, const int* in_sizes, int n_in,
                              void* d_out, int out_size)
{
    const float* x      = (const float*)d_in[0];
    // d_in[1] = mask (causal tril, hardcoded in attn kernel)
    const float* qkv_w  = (const float*)d_in[2];
    const float* qkv_b  = (const float*)d_in[3];
    const float* proj_w = (const float*)d_in[4];
    const float* proj_b = (const float*)d_in[5];
    const float* ln1_g  = (const float*)d_in[6];
    const float* ln1_b  = (const float*)d_in[7];
    const float* ln2_g  = (const float*)d_in[8];
    const float* ln2_b  = (const float*)d_in[9];
    const float* w1     = (const float*)d_in[10];
    const float* w2     = (const float*)d_in[11];
    const float* w3     = (const float*)d_in[12];
    float* out = (float*)d_out;

    float *h, *qkv, *attn, *x1, *b1, *b3;
    cudaGetSymbolAddress((void**)&h,    g_h);
    cudaGetSymbolAddress((void**)&qkv,  g_qkv);
    cudaGetSymbolAddress((void**)&attn, g_attn);
    cudaGetSymbolAddress((void**)&x1,   g_x1);
    cudaGetSymbolAddress((void**)&b1,   g_g1);
    cudaGetSymbolAddress((void**)&b3,   g_g3);

    static bool attr_done = false;
    cudaFuncSetAttribute(attn_kernel,
                         cudaFuncAttributeMaxDynamicSharedMemorySize, ATT_SMEM);
    (void)attr_done;

    // 1. LN1
    ln_kernel<<<MROWS, 256>>>(x, ln1_g, ln1_b, h);
    // 2. qkv = h @ qkv_w^T + qkv_b           [8192, 3072]
    gemm_nt_kernel<<<dim3(3 * CC / 128, MROWS / 128), 256>>>(
        h, qkv_w, qkv_b, nullptr, qkv, MROWS, 3 * CC, CC);
    // 3. causal flash attention
    attn_kernel<<<dim3(NN / 64, BB * HH), 256, ATT_SMEM>>>(qkv, attn);
    // 4. x1 = x + attn @ proj_w^T + proj_b   [8192, 1024]
    gemm_nt_kernel<<<dim3(CC / 128, MROWS / 128), 256>>>(
        attn, proj_w, proj_b, x, x1, MROWS, CC, CC);
    // 5. LN2
    ln_kernel<<<MROWS, 256>>>(x1, ln2_g, ln2_b, h);
    // 6. b1 = h @ w1^T                        [8192, 4096]
    gemm_nt_kernel<<<dim3(FFD / 128, MROWS / 128), 256>>>(
        h, w1, nullptr, nullptr, b1, MROWS, FFD, CC);
    // 7. b3 = h @ w3^T                        [8192, 4096]
    gemm_nt_kernel<<<dim3(FFD / 128, MROWS / 128), 256>>>(
        h, w3, nullptr, nullptr, b3, MROWS, FFD, CC);
    // 8. b1 = silu(b1) * b3
    glu_kernel<<<(MROWS * FFD) / (256 * 4), 256>>>(b1, b3);
    // 9. out = x1 + b1 @ w2^T                 [8192, 1024]
    gemm_nt_kernel<<<dim3(CC / 128, MROWS / 128), 256>>>(
        b1, w2, nullptr, x1, out, MROWS, CC, FFD);
}

// round 6
// speedup vs baseline: 2.1293x; 2.1293x over previous
#include <cuda_runtime.h>
#include <math.h>
#include <stdint.h>

// Problem constants
#define BB 4
#define NN 2048
#define CC 1024
#define HH 16
#define DD 64
#define FFD 4096
#define MROWS (BB * NN)   // 8192

// -------------------- scratch (allocation-free: __device__ globals) ---------
__device__ float g_h[MROWS * CC];        // LN output (reused for LN1 and LN2)
__device__ float g_qkv[MROWS * 3 * CC];  // qkv projection
__device__ float g_attn[MROWS * CC];     // attention output (pre-proj)
__device__ float g_x1[MROWS * CC];       // x + attn_proj
__device__ float g_g1[MROWS * FFD];      // h @ w1^T, then gated product
__device__ float g_g3[MROWS * FFD];      // h @ w3^T

// ======================= portable PTX helpers (sm_80+) ======================
__device__ __forceinline__ uint32_t f32_to_tf32(float x) {
    uint32_t u;
    asm("cvt.rna.tf32.f32 %0, %1;" : "=r"(u) : "f"(x));
    return u;
}
__device__ __forceinline__ void cpa16(uint32_t dst, const void* src) {
    asm volatile("cp.async.ca.shared.global [%0], [%1], 16;"
                 :: "r"(dst), "l"(src));
}
#define CPA_COMMIT() asm volatile("cp.async.commit_group;" ::: "memory")
#define CPA_WAIT1()  asm volatile("cp.async.wait_group 1;" ::: "memory")

__device__ __forceinline__ void mma_tf32(
    float* d, const uint32_t* a, uint32_t b0, uint32_t b1)
{
    asm volatile(
        "mma.sync.aligned.m16n8k8.row.col.f32.tf32.tf32.f32 "
        "{%0,%1,%2,%3}, {%4,%5,%6,%7}, {%8,%9}, {%0,%1,%2,%3};"
        : "+f"(d[0]), "+f"(d[1]), "+f"(d[2]), "+f"(d[3])
        : "r"(a[0]), "r"(a[1]), "r"(a[2]), "r"(a[3]), "r"(b0), "r"(b1));
}

// ============================================================================
// LayerNorm: one row (C=1024) per block, 256 threads, 1 float4/thread.
// ============================================================================
__global__ __launch_bounds__(256) void ln_kernel(
    const float* __restrict__ x, const float* __restrict__ g,
    const float* __restrict__ bta, float* __restrict__ out)
{
    __shared__ float ssum[8], ssq[8];
    const int row = blockIdx.x;
    const int tid = threadIdx.x;

    const float4 v = *(const float4*)(x + (size_t)row * CC + tid * 4);
    float s = v.x + v.y + v.z + v.w;
    float q = v.x * v.x + v.y * v.y + v.z * v.z + v.w * v.w;

    #pragma unroll
    for (int off = 16; off; off >>= 1) {
        s += __shfl_xor_sync(0xffffffffu, s, off);
        q += __shfl_xor_sync(0xffffffffu, q, off);
    }
    if ((tid & 31) == 0) { ssum[tid >> 5] = s; ssq[tid >> 5] = q; }
    __syncthreads();

    float ts = 0.f, tq = 0.f;
    #pragma unroll
    for (int i = 0; i < 8; i++) { ts += ssum[i]; tq += ssq[i]; }

    const float mean = ts * (1.f / (float)CC);
    const float var  = tq * (1.f / (float)CC) - mean * mean;
    const float r    = rsqrtf(var + 1e-6f);

    const float4 gg = *(const float4*)(g + tid * 4);
    const float4 bb = *(const float4*)(bta + tid * 4);
    float4 o;
    o.x = (v.x - mean) * r * gg.x + bb.x;
    o.y = (v.y - mean) * r * gg.y + bb.y;
    o.z = (v.z - mean) * r * gg.z + bb.z;
    o.w = (v.w - mean) * r * gg.w + bb.w;
    *(float4*)(out + (size_t)row * CC + tid * 4) = o;
}

// ============================================================================
// tf32 tensor-core GEMM (NT): C[M,N]=A[M,K]@B[N,K]^T (+bias[N]) (+res[M,N])
// mma.sync.m16n8k8, 128x128 CTA tile, 8 warps (64x32 warp tile... layout:
// warpR=wid&3 owns 32 rows, warpC=wid>>2 owns 64 cols), K-chunk 16,
// 2-stage cp.async pipeline. smem row stride 20 floats (conflict-free).
// ============================================================================
#define KC 16
#define STR 20

__global__ __launch_bounds__(256) void gemm_tc_kernel(
    const float* __restrict__ A, const float* __restrict__ B,
    const float* __restrict__ bias, const float* __restrict__ res,
    float* __restrict__ C, int M, int N, int K)
{
    __shared__ float smA[2][128 * STR];
    __shared__ float smB[2][128 * STR];

    const int tid = threadIdx.x;
    const int wid = tid >> 5, lane = tid & 31;
    const int g = lane >> 2, qd = lane & 3;
    const int warpR = wid & 3, warpC = wid >> 2;
    const int m0 = blockIdx.y * 128, n0 = blockIdx.x * 128;

    const float* Abase = A + (size_t)m0 * K;
    const float* Bbase = B + (size_t)n0 * K;

    // cp.async chunk assignment: 512 16B-chunks per tile, 2 per thread.
    const int ch0 = tid, ch1 = tid + 256;
    const int r0c = ch0 >> 2, c0c = (ch0 & 3) << 2;
    const int r1c = ch1 >> 2, c1c = (ch1 & 3) << 2;

    uint32_t sA[2], sB[2];
    sA[0] = (uint32_t)__cvta_generic_to_shared(&smA[0][0]);
    sA[1] = (uint32_t)__cvta_generic_to_shared(&smA[1][0]);
    sB[0] = (uint32_t)__cvta_generic_to_shared(&smB[0][0]);
    sB[1] = (uint32_t)__cvta_generic_to_shared(&smB[1][0]);

    float acc[2][8][4];
    #pragma unroll
    for (int mi = 0; mi < 2; mi++)
        #pragma unroll
        for (int nj = 0; nj < 8; nj++)
            #pragma unroll
            for (int e = 0; e < 4; e++) acc[mi][nj][e] = 0.f;

    const int nk = K / KC;

    // prefetch stages 0 and 1
    #pragma unroll
    for (int p = 0; p < 2; p++) {
        const int k0 = p * KC;
        cpa16(sA[p] + (uint32_t)(r0c * STR + c0c) * 4, Abase + (size_t)r0c * K + k0 + c0c);
        cpa16(sA[p] + (uint32_t)(r1c * STR + c1c) * 4, Abase + (size_t)r1c * K + k0 + c1c);
        cpa16(sB[p] + (uint32_t)(r0c * STR + c0c) * 4, Bbase + (size_t)r0c * K + k0 + c0c);
        cpa16(sB[p] + (uint32_t)(r1c * STR + c1c) * 4, Bbase + (size_t)r1c * K + k0 + c1c);
        CPA_COMMIT();
    }

    for (int kt = 0; kt < nk; kt++) {
        CPA_WAIT1();
        __syncthreads();
        const int s = kt & 1;
        const float* As = smA[s];
        const float* Bs = smB[s];

        #pragma unroll
        for (int ks = 0; ks < 2; ks++) {
            const int kc0 = ks * 8 + qd;
            uint32_t af[2][4];
            #pragma unroll
            for (int mi = 0; mi < 2; mi++) {
                const int rb = (warpR * 32 + mi * 16 + g) * STR;
                af[mi][0] = f32_to_tf32(As[rb + kc0]);
                af[mi][1] = f32_to_tf32(As[rb + 8 * STR + kc0]);
                af[mi][2] = f32_to_tf32(As[rb + kc0 + 4]);
                af[mi][3] = f32_to_tf32(As[rb + 8 * STR + kc0 + 4]);
            }
            #pragma unroll
            for (int nj = 0; nj < 8; nj++) {
                const int nb = (warpC * 64 + nj * 8 + g) * STR;
                const uint32_t b0 = f32_to_tf32(Bs[nb + kc0]);
                const uint32_t b1 = f32_to_tf32(Bs[nb + kc0 + 4]);
                mma_tf32(acc[0][nj], af[0], b0, b1);
                mma_tf32(acc[1][nj], af[1], b0, b1);
            }
        }
        __syncthreads();

        // prefetch kt+2 into stage s
        if (kt + 2 < nk) {
            const int k0 = (kt + 2) * KC;
            cpa16(sA[s] + (uint32_t)(r0c * STR + c0c) * 4, Abase + (size_t)r0c * K + k0 + c0c);
            cpa16(sA[s] + (uint32_t)(r1c * STR + c1c) * 4, Abase + (size_t)r1c * K + k0 + c1c);
            cpa16(sB[s] + (uint32_t)(r0c * STR + c0c) * 4, Bbase + (size_t)r0c * K + k0 + c0c);
            cpa16(sB[s] + (uint32_t)(r1c * STR + c1c) * 4, Bbase + (size_t)r1c * K + k0 + c1c);
        }
        CPA_COMMIT();
    }

    // epilogue: c frag (mi,nj): rows base+{g, g+8}, cols nj*8 + 2*qd + {0,1}
    #pragma unroll
    for (int mi = 0; mi < 2; mi++) {
        const int rowa = m0 + warpR * 32 + mi * 16 + g;
        #pragma unroll
        for (int nj = 0; nj < 8; nj++) {
            const int col = n0 + warpC * 64 + nj * 8 + 2 * qd;
            float2 v0 = make_float2(acc[mi][nj][0], acc[mi][nj][1]);
            float2 v1 = make_float2(acc[mi][nj][2], acc[mi][nj][3]);
            if (bias) {
                const float bx = bias[col], by = bias[col + 1];
                v0.x += bx; v0.y += by;
                v1.x += bx; v1.y += by;
            }
            if (res) {
                float2 r0 = *(const float2*)(res + (size_t)rowa * N + col);
                float2 r1 = *(const float2*)(res + (size_t)(rowa + 8) * N + col);
                v0.x += r0.x; v0.y += r0.y;
                v1.x += r1.x; v1.y += r1.y;
            }
            *(float2*)(C + (size_t)rowa * N + col) = v0;
            *(float2*)(C + (size_t)(rowa + 8) * N + col) = v1;
        }
    }
}

// ============================================================================
// Flash attention (causal), fp32. Br=Bc=64, D=64. 256 threads, 4x4 thread tile.
// ============================================================================
#define ATT_STR 68
#define ATT_SMEM (3 * 64 * ATT_STR * 4)

__global__ __launch_bounds__(256) void attn_kernel(
    const float* __restrict__ qkv, float* __restrict__ out)
{
    extern __shared__ float sm[];
    float* Qs = sm;                       // [64][68], pre-scaled by 1/8
    float* KT = sm + 64 * ATT_STR;        // [d][c], reused as P[r][k]
    float* Vs = sm + 2 * 64 * ATT_STR;    // [c][d]

    const int tid = threadIdx.x;
    const int tx = tid & 15, ty = tid >> 4;
    const int qb = blockIdx.x;
    const int bh = blockIdx.y;
    const int b = bh >> 4, h = bh & 15;
    const int i0 = qb << 6;
    const size_t base = (size_t)b * NN * (3 * CC) + h * DD;

    #pragma unroll
    for (int l = 0; l < 4; l++) {
        int f = tid + l * 256;
        int r = f >> 4, c = (f & 15) << 2;
        float4 v = *(const float4*)(qkv + base + (size_t)(i0 + r) * (3 * CC) + c);
        v.x *= 0.125f; v.y *= 0.125f; v.z *= 0.125f; v.w *= 0.125f;
        *(float4*)&Qs[r * ATT_STR + c] = v;
    }

    float mrow[4], lrow[4], o[4][4];
    #pragma unroll
    for (int i = 0; i < 4; i++) {
        mrow[i] = -1e30f; lrow[i] = 0.f;
        #pragma unroll
        for (int j = 0; j < 4; j++) o[i][j] = 0.f;
    }

    for (int kb = 0; kb <= qb; kb++) {
        const int k0 = kb << 6;
        __syncthreads();
        #pragma unroll
        for (int l = 0; l < 4; l++) {
            int f = tid + l * 256;
            int c = f >> 4, d = (f & 15) << 2;
            float4 kv = *(const float4*)(qkv + base + CC + (size_t)(k0 + c) * (3 * CC) + d);
            KT[(d + 0) * ATT_STR + c] = kv.x;
            KT[(d + 1) * ATT_STR + c] = kv.y;
            KT[(d + 2) * ATT_STR + c] = kv.z;
            KT[(d + 3) * ATT_STR + c] = kv.w;
            float4 vv = *(const float4*)(qkv + base + 2 * CC + (size_t)(k0 + c) * (3 * CC) + d);
            *(float4*)&Vs[c * ATT_STR + d] = vv;
        }
        __syncthreads();

        float s[4][4];
        #pragma unroll
        for (int i = 0; i < 4; i++)
            #pragma unroll
            for (int j = 0; j < 4; j++) s[i][j] = 0.f;

        #pragma unroll 16
        for (int d = 0; d < 64; d++) {
            float4 kf = *(const float4*)&KT[d * ATT_STR + (tx << 2)];
            float q0 = Qs[(ty * 4 + 0) * ATT_STR + d];
            float q1 = Qs[(ty * 4 + 1) * ATT_STR + d];
            float q2 = Qs[(ty * 4 + 2) * ATT_STR + d];
            float q3 = Qs[(ty * 4 + 3) * ATT_STR + d];
            s[0][0] += q0 * kf.x; s[0][1] += q0 * kf.y; s[0][2] += q0 * kf.z; s[0][3] += q0 * kf.w;
            s[1][0] += q1 * kf.x; s[1][1] += q1 * kf.y; s[1][2] += q1 * kf.z; s[1][3] += q1 * kf.w;
            s[2][0] += q2 * kf.x; s[2][1] += q2 * kf.y; s[2][2] += q2 * kf.z; s[2][3] += q2 * kf.w;
            s[3][0] += q3 * kf.x; s[3][1] += q3 * kf.y; s[3][2] += q3 * kf.z; s[3][3] += q3 * kf.w;
        }

        if (kb == qb) {
            #pragma unroll
            for (int i = 0; i < 4; i++)
                #pragma unroll
                for (int j = 0; j < 4; j++)
                    if (k0 + (tx << 2) + j > i0 + (ty << 2) + i) s[i][j] = -1e30f;
        }

        #pragma unroll
        for (int i = 0; i < 4; i++) {
            float mx = fmaxf(fmaxf(s[i][0], s[i][1]), fmaxf(s[i][2], s[i][3]));
            #pragma unroll
            for (int off = 8; off; off >>= 1)
                mx = fmaxf(mx, __shfl_xor_sync(0xffffffffu, mx, off));
            const float mn = fmaxf(mrow[i], mx);
            const float alpha = __expf(mrow[i] - mn);
            mrow[i] = mn;
            float rs = 0.f;
            #pragma unroll
            for (int j = 0; j < 4; j++) { s[i][j] = __expf(s[i][j] - mn); rs += s[i][j]; }
            #pragma unroll
            for (int off = 8; off; off >>= 1)
                rs += __shfl_xor_sync(0xffffffffu, rs, off);
            lrow[i] = lrow[i] * alpha + rs;
            o[i][0] *= alpha; o[i][1] *= alpha; o[i][2] *= alpha; o[i][3] *= alpha;
        }

        __syncthreads();
        #pragma unroll
        for (int i = 0; i < 4; i++) {
            float4 pv = make_float4(s[i][0], s[i][1], s[i][2], s[i][3]);
            *(float4*)&KT[(ty * 4 + i) * ATT_STR + (tx << 2)] = pv;
        }
        __syncthreads();

        #pragma unroll 16
        for (int k = 0; k < 64; k++) {
            float4 vf = *(const float4*)&Vs[k * ATT_STR + (tx << 2)];
            float p0 = KT[(ty * 4 + 0) * ATT_STR + k];
            float p1 = KT[(ty * 4 + 1) * ATT_STR + k];
            float p2 = KT[(ty * 4 + 2) * ATT_STR + k];
            float p3 = KT[(ty * 4 + 3) * ATT_STR + k];
            o[0][0] += p0 * vf.x; o[0][1] += p0 * vf.y; o[0][2] += p0 * vf.z; o[0][3] += p0 * vf.w;
            o[1][0] += p1 * vf.x; o[1][1] += p1 * vf.y; o[1][2] += p1 * vf.z; o[1][3] += p1 * vf.w;
            o[2][0] += p2 * vf.x; o[2][1] += p2 * vf.y; o[2][2] += p2 * vf.z; o[2][3] += p2 * vf.w;
            o[3][0] += p3 * vf.x; o[3][1] += p3 * vf.y; o[3][2] += p3 * vf.z; o[3][3] += p3 * vf.w;
        }
    }

    #pragma unroll
    for (int i = 0; i < 4; i++) {
        const float inv = 1.f / lrow[i];
        float4 ov = make_float4(o[i][0] * inv, o[i][1] * inv, o[i][2] * inv, o[i][3] * inv);
        *(float4*)(out + (size_t)(b * NN + i0 + ty * 4 + i) * CC + h * DD + (tx << 2)) = ov;
    }
}

// ============================================================================
// SwiGLU gate: a = silu(a) * c, in place over a.
// ============================================================================
__global__ __launch_bounds__(256) void glu_kernel(
    float* __restrict__ a, const float* __restrict__ c)
{
    const size_t i = ((size_t)blockIdx.x * 256 + threadIdx.x) * 4;
    float4 v = *(const float4*)(a + i);
    float4 g = *(const float4*)(c + i);
    v.x = v.x * g.x / (1.f + __expf(-v.x));
    v.y = v.y * g.y / (1.f + __expf(-v.y));
    v.z = v.z * g.z / (1.f + __expf(-v.z));
    v.w = v.w * g.w / (1.f + __expf(-v.w));
    *(float4*)(a + i) = v;
}

// ============================================================================
// Launch
// ============================================================================
extern "C" void kernel_launch(void* const* d_in, const int* in_sizes, int n_in,
                              void* d_out, int out_size)
{
    const float* x      = (const float*)d_in[0];
    // d_in[1] = mask (causal tril, hardcoded in attn kernel)
    const float* qkv_w  = (const float*)d_in[2];
    const float* qkv_b  = (const float*)d_in[3];
    const float* proj_w = (const float*)d_in[4];
    const float* proj_b = (const float*)d_in[5];
    const float* ln1_g  = (const float*)d_in[6];
    const float* ln1_b  = (const float*)d_in[7];
    const float* ln2_g  = (const float*)d_in[8];
    const float* ln2_b  = (const float*)d_in[9];
    const float* w1     = (const float*)d_in[10];
    const float* w2     = (const float*)d_in[11];
    const float* w3     = (const float*)d_in[12];
    float* out = (float*)d_out;

    float *h, *qkv, *attn, *x1, *b1, *b3;
    cudaGetSymbolAddress((void**)&h,    g_h);
    cudaGetSymbolAddress((void**)&qkv,  g_qkv);
    cudaGetSymbolAddress((void**)&attn, g_attn);
    cudaGetSymbolAddress((void**)&x1,   g_x1);
    cudaGetSymbolAddress((void**)&b1,   g_g1);
    cudaGetSymbolAddress((void**)&b3,   g_g3);

    cudaFuncSetAttribute(attn_kernel,
                         cudaFuncAttributeMaxDynamicSharedMemorySize, ATT_SMEM);

    // 1. LN1
    ln_kernel<<<MROWS, 256>>>(x, ln1_g, ln1_b, h);
    // 2. qkv = h @ qkv_w^T + qkv_b           [8192, 3072]
    gemm_tc_kernel<<<dim3(3 * CC / 128, MROWS / 128), 256>>>(
        h, qkv_w, qkv_b, nullptr, qkv, MROWS, 3 * CC, CC);
    // 3. causal flash attention
    attn_kernel<<<dim3(NN / 64, BB * HH), 256, ATT_SMEM>>>(qkv, attn);
    // 4. x1 = x + attn @ proj_w^T + proj_b   [8192, 1024]
    gemm_tc_kernel<<<dim3(CC / 128, MROWS / 128), 256>>>(
        attn, proj_w, proj_b, x, x1, MROWS, CC, CC);
    // 5. LN2
    ln_kernel<<<MROWS, 256>>>(x1, ln2_g, ln2_b, h);
    // 6. b1 = h @ w1^T                        [8192, 4096]
    gemm_tc_kernel<<<dim3(FFD / 128, MROWS / 128), 256>>>(
        h, w1, nullptr, nullptr, b1, MROWS, FFD, CC);
    // 7. b3 = h @ w3^T                        [8192, 4096]
    gemm_tc_kernel<<<dim3(FFD / 128, MROWS / 128), 256>>>(
        h, w3, nullptr, nullptr, b3, MROWS, FFD, CC);
    // 8. b1 = silu(b1) * b3
    glu_kernel<<<(MROWS * FFD) / (256 * 4), 256>>>(b1, b3);
    // 9. out = x1 + b1 @ w2^T                 [8192, 1024]
    gemm_tc_kernel<<<dim3(CC / 128, MROWS / 128), 256>>>(
        b1, w2, nullptr, x1, out, MROWS, CC, FFD);
}

// round 7
// speedup vs baseline: 2.8275x; 1.3279x over previous
#include <cuda_runtime.h>
#include <math.h>
#include <stdint.h>

// Problem constants
#define BB 4
#define NN 2048
#define CC 1024
#define HH 16
#define DD 64
#define FFD 4096
#define MROWS (BB * NN)   // 8192

// -------------------- scratch (allocation-free: __device__ globals) ---------
__device__ float g_h[MROWS * CC];        // LN output (reused for LN1 and LN2)
__device__ float g_qkv[MROWS * 3 * CC];  // qkv projection
__device__ float g_attn[MROWS * CC];     // attention output (pre-proj)
__device__ float g_x1[MROWS * CC];       // x + attn_proj
__device__ float g_g1[MROWS * FFD];      // h @ w1^T, then gated product
__device__ float g_g3[MROWS * FFD];      // h @ w3^T

// ======================= portable PTX helpers (sm_80+) ======================
__device__ __forceinline__ uint32_t f32_to_tf32(float x) {
    uint32_t u;
    asm("cvt.rna.tf32.f32 %0, %1;" : "=r"(u) : "f"(x));
    return u;
}

__device__ __forceinline__ void mma_tf32(
    float* d, const uint32_t* a, uint32_t b0, uint32_t b1)
{
    asm volatile(
        "mma.sync.aligned.m16n8k8.row.col.f32.tf32.tf32.f32 "
        "{%0,%1,%2,%3}, {%4,%5,%6,%7}, {%8,%9}, {%0,%1,%2,%3};"
        : "+f"(d[0]), "+f"(d[1]), "+f"(d[2]), "+f"(d[3])
        : "r"(a[0]), "r"(a[1]), "r"(a[2]), "r"(a[3]), "r"(b0), "r"(b1));
}

// ============================================================================
// LayerNorm: one row (C=1024) per block, 256 threads, 1 float4/thread.
// ============================================================================
__global__ __launch_bounds__(256) void ln_kernel(
    const float* __restrict__ x, const float* __restrict__ g,
    const float* __restrict__ bta, float* __restrict__ out)
{
    __shared__ float ssum[8], ssq[8];
    const int row = blockIdx.x;
    const int tid = threadIdx.x;

    const float4 v = *(const float4*)(x + (size_t)row * CC + tid * 4);
    float s = v.x + v.y + v.z + v.w;
    float q = v.x * v.x + v.y * v.y + v.z * v.z + v.w * v.w;

    #pragma unroll
    for (int off = 16; off; off >>= 1) {
        s += __shfl_xor_sync(0xffffffffu, s, off);
        q += __shfl_xor_sync(0xffffffffu, q, off);
    }
    if ((tid & 31) == 0) { ssum[tid >> 5] = s; ssq[tid >> 5] = q; }
    __syncthreads();

    float ts = 0.f, tq = 0.f;
    #pragma unroll
    for (int i = 0; i < 8; i++) { ts += ssum[i]; tq += ssq[i]; }

    const float mean = ts * (1.f / (float)CC);
    const float var  = tq * (1.f / (float)CC) - mean * mean;
    const float r    = rsqrtf(var + 1e-6f);

    const float4 gg = *(const float4*)(g + tid * 4);
    const float4 bb = *(const float4*)(bta + tid * 4);
    float4 o;
    o.x = (v.x - mean) * r * gg.x + bb.x;
    o.y = (v.y - mean) * r * gg.y + bb.y;
    o.z = (v.z - mean) * r * gg.z + bb.z;
    o.w = (v.w - mean) * r * gg.w + bb.w;
    *(float4*)(out + (size_t)row * CC + tid * 4) = o;
}

// ============================================================================
// tf32 tensor-core GEMM (NT): C[M,N]=A[M,K]@B[N,K]^T (+bias[N]) (+res[M,N])
// mma.sync.m16n8k8, 128x128 CTA tile, 8 warps. K-chunk 16.
// LDG->reg double buffer; tf32 conversion ONCE on the STS path; inner loop
// reads tf32 bits straight from smem (no cvt on the critical path).
// ============================================================================
#define KC 16
#define STR 20

__global__ __launch_bounds__(256) void gemm_tc_kernel(
    const float* __restrict__ A, const float* __restrict__ B,
    const float* __restrict__ bias, const float* __restrict__ res,
    float* __restrict__ C, int M, int N, int K)
{
    __shared__ uint32_t smA[2][128 * STR];
    __shared__ uint32_t smB[2][128 * STR];

    const int tid = threadIdx.x;
    const int wid = tid >> 5, lane = tid & 31;
    const int g = lane >> 2, qd = lane & 3;
    const int warpR = wid & 3, warpC = wid >> 2;
    const int m0 = blockIdx.y * 128, n0 = blockIdx.x * 128;

    const float* Abase = A + (size_t)m0 * K;
    const float* Bbase = B + (size_t)n0 * K;

    // 512 16B-chunks per 128x16 tile, 2 per thread
    const int r0c = tid >> 2, c0c = (tid & 3) << 2;
    const int r1c = (tid + 256) >> 2, c1c = ((tid + 256) & 3) << 2;

    float acc[2][8][4];
    #pragma unroll
    for (int mi = 0; mi < 2; mi++)
        #pragma unroll
        for (int nj = 0; nj < 8; nj++)
            #pragma unroll
            for (int e = 0; e < 4; e++) acc[mi][nj][e] = 0.f;

    const int nk = K / KC;

    // prologue: load k-chunk 0, convert, store to stage 0
    float4 a0 = *(const float4*)(Abase + (size_t)r0c * K + c0c);
    float4 a1 = *(const float4*)(Abase + (size_t)r1c * K + c1c);
    float4 b0 = *(const float4*)(Bbase + (size_t)r0c * K + c0c);
    float4 b1 = *(const float4*)(Bbase + (size_t)r1c * K + c1c);
    {
        uint4 t;
        t.x = f32_to_tf32(a0.x); t.y = f32_to_tf32(a0.y);
        t.z = f32_to_tf32(a0.z); t.w = f32_to_tf32(a0.w);
        *(uint4*)&smA[0][r0c * STR + c0c] = t;
        t.x = f32_to_tf32(a1.x); t.y = f32_to_tf32(a1.y);
        t.z = f32_to_tf32(a1.z); t.w = f32_to_tf32(a1.w);
        *(uint4*)&smA[0][r1c * STR + c1c] = t;
        t.x = f32_to_tf32(b0.x); t.y = f32_to_tf32(b0.y);
        t.z = f32_to_tf32(b0.z); t.w = f32_to_tf32(b0.w);
        *(uint4*)&smB[0][r0c * STR + c0c] = t;
        t.x = f32_to_tf32(b1.x); t.y = f32_to_tf32(b1.y);
        t.z = f32_to_tf32(b1.z); t.w = f32_to_tf32(b1.w);
        *(uint4*)&smB[0][r1c * STR + c1c] = t;
    }
    __syncthreads();

    for (int kt = 0; kt < nk; kt++) {
        const int s = kt & 1;
        // issue LDGs for next k-chunk early (latency hidden by MMA work)
        if (kt + 1 < nk) {
            const int k0 = (kt + 1) * KC;
            a0 = *(const float4*)(Abase + (size_t)r0c * K + k0 + c0c);
            a1 = *(const float4*)(Abase + (size_t)r1c * K + k0 + c1c);
            b0 = *(const float4*)(Bbase + (size_t)r0c * K + k0 + c0c);
            b1 = *(const float4*)(Bbase + (size_t)r1c * K + k0 + c1c);
        }

        const uint32_t* As = smA[s];
        const uint32_t* Bs = smB[s];
        #pragma unroll
        for (int ks = 0; ks < 2; ks++) {
            const int kc0 = ks * 8 + qd;
            uint32_t af[2][4];
            #pragma unroll
            for (int mi = 0; mi < 2; mi++) {
                const int rb = (warpR * 32 + mi * 16 + g) * STR;
                af[mi][0] = As[rb + kc0];
                af[mi][1] = As[rb + 8 * STR + kc0];
                af[mi][2] = As[rb + kc0 + 4];
                af[mi][3] = As[rb + 8 * STR + kc0 + 4];
            }
            #pragma unroll
            for (int nj = 0; nj < 8; nj++) {
                const int nb = (warpC * 64 + nj * 8 + g) * STR;
                const uint32_t bb0 = Bs[nb + kc0];
                const uint32_t bb1 = Bs[nb + kc0 + 4];
                mma_tf32(acc[0][nj], af[0], bb0, bb1);
                mma_tf32(acc[1][nj], af[1], bb0, bb1);
            }
        }

        if (kt + 1 < nk) {
            const int d = s ^ 1;
            uint4 t;
            t.x = f32_to_tf32(a0.x); t.y = f32_to_tf32(a0.y);
            t.z = f32_to_tf32(a0.z); t.w = f32_to_tf32(a0.w);
            *(uint4*)&smA[d][r0c * STR + c0c] = t;
            t.x = f32_to_tf32(a1.x); t.y = f32_to_tf32(a1.y);
            t.z = f32_to_tf32(a1.z); t.w = f32_to_tf32(a1.w);
            *(uint4*)&smA[d][r1c * STR + c1c] = t;
            t.x = f32_to_tf32(b0.x); t.y = f32_to_tf32(b0.y);
            t.z = f32_to_tf32(b0.z); t.w = f32_to_tf32(b0.w);
            *(uint4*)&smB[d][r0c * STR + c0c] = t;
            t.x = f32_to_tf32(b1.x); t.y = f32_to_tf32(b1.y);
            t.z = f32_to_tf32(b1.z); t.w = f32_to_tf32(b1.w);
            *(uint4*)&smB[d][r1c * STR + c1c] = t;
            __syncthreads();
        }
    }

    // epilogue
    #pragma unroll
    for (int mi = 0; mi < 2; mi++) {
        const int rowa = m0 + warpR * 32 + mi * 16 + g;
        #pragma unroll
        for (int nj = 0; nj < 8; nj++) {
            const int col = n0 + warpC * 64 + nj * 8 + 2 * qd;
            float2 v0 = make_float2(acc[mi][nj][0], acc[mi][nj][1]);
            float2 v1 = make_float2(acc[mi][nj][2], acc[mi][nj][3]);
            if (bias) {
                const float bx = bias[col], by = bias[col + 1];
                v0.x += bx; v0.y += by;
                v1.x += bx; v1.y += by;
            }
            if (res) {
                float2 r0 = *(const float2*)(res + (size_t)rowa * N + col);
                float2 r1 = *(const float2*)(res + (size_t)(rowa + 8) * N + col);
                v0.x += r0.x; v0.y += r0.y;
                v1.x += r1.x; v1.y += r1.y;
            }
            *(float2*)(C + (size_t)rowa * N + col) = v0;
            *(float2*)(C + (size_t)(rowa + 8) * N + col) = v1;
        }
    }
}

// ============================================================================
// Tensor-core flash attention (causal), tf32 MMA + fp32 softmax.
// 128 threads (4 warps). Br=Bc=64, D=64. Warp w owns Q rows [w*16, w*16+16).
// smem (tf32 bits): Qs[64][68] | Ks[64][68] | Ps[64][68] | Vs[64][72]
// Strides: 68 -> A/B frag reads conflict-free; 72 -> V (B-frag by k) c-f.
// ============================================================================
#define AST 68
#define VST 72
#define ATT_SMEM ((3 * 64 * AST + 64 * VST) * 4)

__global__ __launch_bounds__(128) void attn_kernel(
    const float* __restrict__ qkv, float* __restrict__ out)
{
    extern __shared__ uint32_t sh[];
    uint32_t* Qs = sh;
    uint32_t* Ks = sh + 64 * AST;
    uint32_t* Ps = sh + 2 * 64 * AST;
    uint32_t* Vs = sh + 3 * 64 * AST;

    const int tid = threadIdx.x;
    const int wid = tid >> 5, lane = tid & 31;
    const int g = lane >> 2, qd = lane & 3;
    const int qb = blockIdx.x;
    const int bh = blockIdx.y;
    const int b = bh >> 4, h = bh & 15;
    const int i0 = qb << 6;
    const size_t base = (size_t)b * NN * (3 * CC) + h * DD;

    // load Q (scaled by 1/8), tf32
    #pragma unroll
    for (int l = 0; l < 8; l++) {
        const int idx = tid + l * 128;
        const int r = idx >> 4, c = (idx & 15) << 2;
        float4 v = *(const float4*)(qkv + base + (size_t)(i0 + r) * (3 * CC) + c);
        uint4 t;
        t.x = f32_to_tf32(v.x * 0.125f); t.y = f32_to_tf32(v.y * 0.125f);
        t.z = f32_to_tf32(v.z * 0.125f); t.w = f32_to_tf32(v.w * 0.125f);
        *(uint4*)&Qs[r * AST + c] = t;
    }

    float o[8][4];
    #pragma unroll
    for (int nj = 0; nj < 8; nj++)
        #pragma unroll
        for (int e = 0; e < 4; e++) o[nj][e] = 0.f;
    float m0 = -1e30f, m1 = -1e30f, l0 = 0.f, l1 = 0.f;

    const int rb = (wid * 16 + g) * AST;

    for (int kb = 0; kb <= qb; kb++) {
        const int k0r = kb << 6;
        __syncthreads();   // prior iter's K/V reads done; 1st iter: Q visible
        #pragma unroll
        for (int l = 0; l < 8; l++) {
            const int idx = tid + l * 128;
            const int c = idx >> 4, d = (idx & 15) << 2;
            float4 kv = *(const float4*)(qkv + base + CC + (size_t)(k0r + c) * (3 * CC) + d);
            uint4 t;
            t.x = f32_to_tf32(kv.x); t.y = f32_to_tf32(kv.y);
            t.z = f32_to_tf32(kv.z); t.w = f32_to_tf32(kv.w);
            *(uint4*)&Ks[c * AST + d] = t;
            float4 vv = *(const float4*)(qkv + base + 2 * CC + (size_t)(k0r + c) * (3 * CC) + d);
            t.x = f32_to_tf32(vv.x); t.y = f32_to_tf32(vv.y);
            t.z = f32_to_tf32(vv.z); t.w = f32_to_tf32(vv.w);
            *(uint4*)&Vs[c * VST + d] = t;
        }
        __syncthreads();

        // ---- S = Q K^T ----
        float s[8][4];
        #pragma unroll
        for (int nj = 0; nj < 8; nj++)
            #pragma unroll
            for (int e = 0; e < 4; e++) s[nj][e] = 0.f;

        #pragma unroll
        for (int ks = 0; ks < 8; ks++) {
            const int kc0 = ks * 8 + qd;
            uint32_t af[4];
            af[0] = Qs[rb + kc0];
            af[1] = Qs[rb + 8 * AST + kc0];
            af[2] = Qs[rb + kc0 + 4];
            af[3] = Qs[rb + 8 * AST + kc0 + 4];
            #pragma unroll
            for (int nj = 0; nj < 8; nj++) {
                const int nb = (nj * 8 + g) * AST;
                mma_tf32(s[nj], af, Ks[nb + kc0], Ks[nb + kc0 + 4]);
            }
        }

        // causal mask on the diagonal block
        if (kb == qb) {
            const int row0 = i0 + wid * 16 + g;
            #pragma unroll
            for (int nj = 0; nj < 8; nj++) {
                const int col = k0r + nj * 8 + 2 * qd;
                if (col > row0)     s[nj][0] = -1e30f;
                if (col + 1 > row0) s[nj][1] = -1e30f;
                if (col > row0 + 8)     s[nj][2] = -1e30f;
                if (col + 1 > row0 + 8) s[nj][3] = -1e30f;
            }
        }

        // ---- online softmax (rows g and g+8 of this warp's tile) ----
        float mx0 = -1e30f, mx1 = -1e30f;
        #pragma unroll
        for (int nj = 0; nj < 8; nj++) {
            mx0 = fmaxf(mx0, fmaxf(s[nj][0], s[nj][1]));
            mx1 = fmaxf(mx1, fmaxf(s[nj][2], s[nj][3]));
        }
        mx0 = fmaxf(mx0, __shfl_xor_sync(0xffffffffu, mx0, 1));
        mx0 = fmaxf(mx0, __shfl_xor_sync(0xffffffffu, mx0, 2));
        mx1 = fmaxf(mx1, __shfl_xor_sync(0xffffffffu, mx1, 1));
        mx1 = fmaxf(mx1, __shfl_xor_sync(0xffffffffu, mx1, 2));

        const float mn0 = fmaxf(m0, mx0), mn1 = fmaxf(m1, mx1);
        const float al0 = __expf(m0 - mn0), al1 = __expf(m1 - mn1);
        m0 = mn0; m1 = mn1;

        float rs0 = 0.f, rs1 = 0.f;
        #pragma unroll
        for (int nj = 0; nj < 8; nj++) {
            s[nj][0] = __expf(s[nj][0] - mn0); rs0 += s[nj][0];
            s[nj][1] = __expf(s[nj][1] - mn0); rs0 += s[nj][1];
            s[nj][2] = __expf(s[nj][2] - mn1); rs1 += s[nj][2];
            s[nj][3] = __expf(s[nj][3] - mn1); rs1 += s[nj][3];
        }
        rs0 += __shfl_xor_sync(0xffffffffu, rs0, 1);
        rs0 += __shfl_xor_sync(0xffffffffu, rs0, 2);
        rs1 += __shfl_xor_sync(0xffffffffu, rs1, 1);
        rs1 += __shfl_xor_sync(0xffffffffu, rs1, 2);
        l0 = l0 * al0 + rs0;
        l1 = l1 * al1 + rs1;

        #pragma unroll
        for (int nj = 0; nj < 8; nj++) {
            o[nj][0] *= al0; o[nj][1] *= al0;
            o[nj][2] *= al1; o[nj][3] *= al1;
        }

        // ---- P -> smem (tf32); warp-local round trip ----
        __syncwarp();
        #pragma unroll
        for (int nj = 0; nj < 8; nj++) {
            const int cb = nj * 8 + 2 * qd;
            Ps[rb + cb]     = f32_to_tf32(s[nj][0]);
            Ps[rb + cb + 1] = f32_to_tf32(s[nj][1]);
            Ps[rb + 8 * AST + cb]     = f32_to_tf32(s[nj][2]);
            Ps[rb + 8 * AST + cb + 1] = f32_to_tf32(s[nj][3]);
        }
        __syncwarp();

        // ---- O += P @ V ----
        #pragma unroll
        for (int ks = 0; ks < 8; ks++) {
            const int kc0 = ks * 8 + qd;
            uint32_t af[4];
            af[0] = Ps[rb + kc0];
            af[1] = Ps[rb + 8 * AST + kc0];
            af[2] = Ps[rb + kc0 + 4];
            af[3] = Ps[rb + 8 * AST + kc0 + 4];
            #pragma unroll
            for (int nj = 0; nj < 8; nj++) {
                mma_tf32(o[nj], af,
                         Vs[kc0 * VST + nj * 8 + g],
                         Vs[(kc0 + 4) * VST + nj * 8 + g]);
            }
        }
    }

    // epilogue
    const float inv0 = 1.f / l0, inv1 = 1.f / l1;
    const int row0 = b * NN + i0 + wid * 16 + g;
    #pragma unroll
    for (int nj = 0; nj < 8; nj++) {
        const int col = h * DD + nj * 8 + 2 * qd;
        *(float2*)(out + (size_t)row0 * CC + col) =
            make_float2(o[nj][0] * inv0, o[nj][1] * inv0);
        *(float2*)(out + (size_t)(row0 + 8) * CC + col) =
            make_float2(o[nj][2] * inv1, o[nj][3] * inv1);
    }
}

// ============================================================================
// SwiGLU gate: a = silu(a) * c, in place over a.
// ============================================================================
__global__ __launch_bounds__(256) void glu_kernel(
    float* __restrict__ a, const float* __restrict__ c)
{
    const size_t i = ((size_t)blockIdx.x * 256 + threadIdx.x) * 4;
    float4 v = *(const float4*)(a + i);
    float4 g = *(const float4*)(c + i);
    v.x = v.x * g.x / (1.f + __expf(-v.x));
    v.y = v.y * g.y / (1.f + __expf(-v.y));
    v.z = v.z * g.z / (1.f + __expf(-v.z));
    v.w = v.w * g.w / (1.f + __expf(-v.w));
    *(float4*)(a + i) = v;
}

// ============================================================================
// Launch
// ============================================================================
extern "C" void kernel_launch(void* const* d_in, const int* in_sizes, int n_in,
                              void* d_out, int out_size)
{
    const float* x      = (const float*)d_in[0];
    // d_in[1] = mask (causal tril, hardcoded in attn kernel)
    const float* qkv_w  = (const float*)d_in[2];
    const float* qkv_b  = (const float*)d_in[3];
    const float* proj_w = (const float*)d_in[4];
    const float* proj_b = (const float*)d_in[5];
    const float* ln1_g  = (const float*)d_in[6];
    const float* ln1_b  = (const float*)d_in[7];
    const float* ln2_g  = (const float*)d_in[8];
    const float* ln2_b  = (const float*)d_in[9];
    const float* w1     = (const float*)d_in[10];
    const float* w2     = (const float*)d_in[11];
    const float* w3     = (const float*)d_in[12];
    float* out = (float*)d_out;

    float *h, *qkv, *attn, *x1, *b1, *b3;
    cudaGetSymbolAddress((void**)&h,    g_h);
    cudaGetSymbolAddress((void**)&qkv,  g_qkv);
    cudaGetSymbolAddress((void**)&attn, g_attn);
    cudaGetSymbolAddress((void**)&x1,   g_x1);
    cudaGetSymbolAddress((void**)&b1,   g_g1);
    cudaGetSymbolAddress((void**)&b3,   g_g3);

    cudaFuncSetAttribute(attn_kernel,
                         cudaFuncAttributeMaxDynamicSharedMemorySize, ATT_SMEM);

    // 1. LN1
    ln_kernel<<<MROWS, 256>>>(x, ln1_g, ln1_b, h);
    // 2. qkv = h @ qkv_w^T + qkv_b           [8192, 3072]
    gemm_tc_kernel<<<dim3(3 * CC / 128, MROWS / 128), 256>>>(
        h, qkv_w, qkv_b, nullptr, qkv, MROWS, 3 * CC, CC);
    // 3. causal flash attention (tensor cores)
    attn_kernel<<<dim3(NN / 64, BB * HH), 128, ATT_SMEM>>>(qkv, attn);
    // 4. x1 = x + attn @ proj_w^T + proj_b   [8192, 1024]
    gemm_tc_kernel<<<dim3(CC / 128, MROWS / 128), 256>>>(
        attn, proj_w, proj_b, x, x1, MROWS, CC, CC);
    // 5. LN2
    ln_kernel<<<MROWS, 256>>>(x1, ln2_g, ln2_b, h);
    // 6. b1 = h @ w1^T                        [8192, 4096]
    gemm_tc_kernel<<<dim3(FFD / 128, MROWS / 128), 256>>>(
        h, w1, nullptr, nullptr, b1, MROWS, FFD, CC);
    // 7. b3 = h @ w3^T                        [8192, 4096]
    gemm_tc_kernel<<<dim3(FFD / 128, MROWS / 128), 256>>>(
        h, w3, nullptr, nullptr, b3, MROWS, FFD, CC);
    // 8. b1 = silu(b1) * b3
    glu_kernel<<<(MROWS * FFD) / (256 * 4), 256>>>(b1, b3);
    // 9. out = x1 + b1 @ w2^T                 [8192, 1024]
    gemm_tc_kernel<<<dim3(CC / 128, MROWS / 128), 256>>>(
        b1, w2, nullptr, x1, out, MROWS, CC, FFD);
}

// round 8
// speedup vs baseline: 2.8519x; 1.0086x over previous
#include <cuda_runtime.h>
#include <math.h>
#include <stdint.h>

// Problem constants
#define BB 4
#define NN 2048
#define CC 1024
#define HH 16
#define DD 64
#define FFD 4096
#define MROWS (BB * NN)   // 8192

// -------------------- scratch (allocation-free: __device__ globals) ---------
__device__ float g_h[MROWS * CC];        // LN output (reused for LN1 and LN2)
__device__ float g_qkv[MROWS * 3 * CC];  // qkv projection
__device__ float g_attn[MROWS * CC];     // attention output (pre-proj)
__device__ float g_x1[MROWS * CC];       // x + attn_proj
__device__ float g_g1[MROWS * FFD];      // h @ w1^T, then gated product
__device__ float g_g3[MROWS * FFD];      // h @ w3^T

// ======================= portable PTX helpers (sm_80+) ======================
__device__ __forceinline__ uint32_t f32_to_tf32(float x) {
    uint32_t u;
    asm("cvt.rna.tf32.f32 %0, %1;" : "=r"(u) : "f"(x));
    return u;
}

__device__ __forceinline__ void mma_tf32(
    float* d, const uint32_t* a, uint32_t b0, uint32_t b1)
{
    asm volatile(
        "mma.sync.aligned.m16n8k8.row.col.f32.tf32.tf32.f32 "
        "{%0,%1,%2,%3}, {%4,%5,%6,%7}, {%8,%9}, {%0,%1,%2,%3};"
        : "+f"(d[0]), "+f"(d[1]), "+f"(d[2]), "+f"(d[3])
        : "r"(a[0]), "r"(a[1]), "r"(a[2]), "r"(a[3]), "r"(b0), "r"(b1));
}

// ============================================================================
// LayerNorm: one row (C=1024) per block, 256 threads, 1 float4/thread.
// ============================================================================
__global__ __launch_bounds__(256) void ln_kernel(
    const float* __restrict__ x, const float* __restrict__ g,
    const float* __restrict__ bta, float* __restrict__ out)
{
    __shared__ float ssum[8], ssq[8];
    const int row = blockIdx.x;
    const int tid = threadIdx.x;

    const float4 v = *(const float4*)(x + (size_t)row * CC + tid * 4);
    float s = v.x + v.y + v.z + v.w;
    float q = v.x * v.x + v.y * v.y + v.z * v.z + v.w * v.w;

    #pragma unroll
    for (int off = 16; off; off >>= 1) {
        s += __shfl_xor_sync(0xffffffffu, s, off);
        q += __shfl_xor_sync(0xffffffffu, q, off);
    }
    if ((tid & 31) == 0) { ssum[tid >> 5] = s; ssq[tid >> 5] = q; }
    __syncthreads();

    float ts = 0.f, tq = 0.f;
    #pragma unroll
    for (int i = 0; i < 8; i++) { ts += ssum[i]; tq += ssq[i]; }

    const float mean = ts * (1.f / (float)CC);
    const float var  = tq * (1.f / (float)CC) - mean * mean;
    const float r    = rsqrtf(var + 1e-6f);

    const float4 gg = *(const float4*)(g + tid * 4);
    const float4 bb = *(const float4*)(bta + tid * 4);
    float4 o;
    o.x = (v.x - mean) * r * gg.x + bb.x;
    o.y = (v.y - mean) * r * gg.y + bb.y;
    o.z = (v.z - mean) * r * gg.z + bb.z;
    o.w = (v.w - mean) * r * gg.w + bb.w;
    *(float4*)(out + (size_t)row * CC + tid * 4) = o;
}

// ============================================================================
// tf32 tensor-core GEMM (NT): C[M,N]=A[M,K]@B[N,K]^T (+bias[N]) (+res[M,N])
// mma.sync.m16n8k8, 128x128 CTA tile, 8 warps. K-chunk 16.
// LDG->reg double buffer; tf32 conversion once on the STS path.
// ============================================================================
#define KC 16
#define STR 20

__global__ __launch_bounds__(256) void gemm_tc_kernel(
    const float* __restrict__ A, const float* __restrict__ B,
    const float* __restrict__ bias, const float* __restrict__ res,
    float* __restrict__ C, int M, int N, int K)
{
    __shared__ uint32_t smA[2][128 * STR];
    __shared__ uint32_t smB[2][128 * STR];

    const int tid = threadIdx.x;
    const int wid = tid >> 5, lane = tid & 31;
    const int g = lane >> 2, qd = lane & 3;
    const int warpR = wid & 3, warpC = wid >> 2;
    const int m0 = blockIdx.y * 128, n0 = blockIdx.x * 128;

    const float* Abase = A + (size_t)m0 * K;
    const float* Bbase = B + (size_t)n0 * K;

    const int r0c = tid >> 2, c0c = (tid & 3) << 2;
    const int r1c = (tid + 256) >> 2, c1c = ((tid + 256) & 3) << 2;

    float acc[2][8][4];
    #pragma unroll
    for (int mi = 0; mi < 2; mi++)
        #pragma unroll
        for (int nj = 0; nj < 8; nj++)
            #pragma unroll
            for (int e = 0; e < 4; e++) acc[mi][nj][e] = 0.f;

    const int nk = K / KC;

    float4 a0 = *(const float4*)(Abase + (size_t)r0c * K + c0c);
    float4 a1 = *(const float4*)(Abase + (size_t)r1c * K + c1c);
    float4 b0 = *(const float4*)(Bbase + (size_t)r0c * K + c0c);
    float4 b1 = *(const float4*)(Bbase + (size_t)r1c * K + c1c);
    {
        uint4 t;
        t.x = f32_to_tf32(a0.x); t.y = f32_to_tf32(a0.y);
        t.z = f32_to_tf32(a0.z); t.w = f32_to_tf32(a0.w);
        *(uint4*)&smA[0][r0c * STR + c0c] = t;
        t.x = f32_to_tf32(a1.x); t.y = f32_to_tf32(a1.y);
        t.z = f32_to_tf32(a1.z); t.w = f32_to_tf32(a1.w);
        *(uint4*)&smA[0][r1c * STR + c1c] = t;
        t.x = f32_to_tf32(b0.x); t.y = f32_to_tf32(b0.y);
        t.z = f32_to_tf32(b0.z); t.w = f32_to_tf32(b0.w);
        *(uint4*)&smB[0][r0c * STR + c0c] = t;
        t.x = f32_to_tf32(b1.x); t.y = f32_to_tf32(b1.y);
        t.z = f32_to_tf32(b1.z); t.w = f32_to_tf32(b1.w);
        *(uint4*)&smB[0][r1c * STR + c1c] = t;
    }
    __syncthreads();

    for (int kt = 0; kt < nk; kt++) {
        const int s = kt & 1;
        if (kt + 1 < nk) {
            const int k0 = (kt + 1) * KC;
            a0 = *(const float4*)(Abase + (size_t)r0c * K + k0 + c0c);
            a1 = *(const float4*)(Abase + (size_t)r1c * K + k0 + c1c);
            b0 = *(const float4*)(Bbase + (size_t)r0c * K + k0 + c0c);
            b1 = *(const float4*)(Bbase + (size_t)r1c * K + k0 + c1c);
        }

        const uint32_t* As = smA[s];
        const uint32_t* Bs = smB[s];
        #pragma unroll
        for (int ks = 0; ks < 2; ks++) {
            const int kc0 = ks * 8 + qd;
            uint32_t af[2][4];
            #pragma unroll
            for (int mi = 0; mi < 2; mi++) {
                const int rb = (warpR * 32 + mi * 16 + g) * STR;
                af[mi][0] = As[rb + kc0];
                af[mi][1] = As[rb + 8 * STR + kc0];
                af[mi][2] = As[rb + kc0 + 4];
                af[mi][3] = As[rb + 8 * STR + kc0 + 4];
            }
            #pragma unroll
            for (int nj = 0; nj < 8; nj++) {
                const int nb = (warpC * 64 + nj * 8 + g) * STR;
                const uint32_t bb0 = Bs[nb + kc0];
                const uint32_t bb1 = Bs[nb + kc0 + 4];
                mma_tf32(acc[0][nj], af[0], bb0, bb1);
                mma_tf32(acc[1][nj], af[1], bb0, bb1);
            }
        }

        if (kt + 1 < nk) {
            const int d = s ^ 1;
            uint4 t;
            t.x = f32_to_tf32(a0.x); t.y = f32_to_tf32(a0.y);
            t.z = f32_to_tf32(a0.z); t.w = f32_to_tf32(a0.w);
            *(uint4*)&smA[d][r0c * STR + c0c] = t;
            t.x = f32_to_tf32(a1.x); t.y = f32_to_tf32(a1.y);
            t.z = f32_to_tf32(a1.z); t.w = f32_to_tf32(a1.w);
            *(uint4*)&smA[d][r1c * STR + c1c] = t;
            t.x = f32_to_tf32(b0.x); t.y = f32_to_tf32(b0.y);
            t.z = f32_to_tf32(b0.z); t.w = f32_to_tf32(b0.w);
            *(uint4*)&smB[d][r0c * STR + c0c] = t;
            t.x = f32_to_tf32(b1.x); t.y = f32_to_tf32(b1.y);
            t.z = f32_to_tf32(b1.z); t.w = f32_to_tf32(b1.w);
            *(uint4*)&smB[d][r1c * STR + c1c] = t;
            __syncthreads();
        }
    }

    #pragma unroll
    for (int mi = 0; mi < 2; mi++) {
        const int rowa = m0 + warpR * 32 + mi * 16 + g;
        #pragma unroll
        for (int nj = 0; nj < 8; nj++) {
            const int col = n0 + warpC * 64 + nj * 8 + 2 * qd;
            float2 v0 = make_float2(acc[mi][nj][0], acc[mi][nj][1]);
            float2 v1 = make_float2(acc[mi][nj][2], acc[mi][nj][3]);
            if (bias) {
                const float bx = bias[col], by = bias[col + 1];
                v0.x += bx; v0.y += by;
                v1.x += bx; v1.y += by;
            }
            if (res) {
                float2 r0 = *(const float2*)(res + (size_t)rowa * N + col);
                float2 r1 = *(const float2*)(res + (size_t)(rowa + 8) * N + col);
                v0.x += r0.x; v0.y += r0.y;
                v1.x += r1.x; v1.y += r1.y;
            }
            *(float2*)(C + (size_t)rowa * N + col) = v0;
            *(float2*)(C + (size_t)(rowa + 8) * N + col) = v1;
        }
    }
}

// ============================================================================
// Tensor-core flash attention v2 (causal), tf32 MMA + fp32 softmax.
// 256 threads (8 warps). Br=128, Bc=64, D=64. Warp w owns Q rows [w*16,w*16+16).
// Double-buffered K/V (LDG->reg prefetch, cvt+STS after compute, 1 sync/iter).
// P: S c-frags -> PV a-frags via intra-quad shuffles (no smem round trip).
// smem (tf32 bits): Qs[128][68] | Ks[2][64][68] | Vs[2][64][72]  = 106.5 KB
// ============================================================================
#define AST 68
#define VST 72
#define ATT_SMEM ((128 * AST + 2 * 64 * AST + 2 * 64 * VST) * 4)

__global__ __launch_bounds__(256) void attn_kernel(
    const float* __restrict__ qkv, float* __restrict__ out)
{
    extern __shared__ uint32_t sh[];
    uint32_t* Qs = sh;                               // 128*AST
    uint32_t* Ks0 = sh + 128 * AST;                  // stage 0
    uint32_t* Ks1 = Ks0 + 64 * AST;                  // stage 1
    uint32_t* Vs0 = Ks1 + 64 * AST;
    uint32_t* Vs1 = Vs0 + 64 * VST;

    const int tid = threadIdx.x;
    const int wid = tid >> 5, lane = tid & 31;
    const int g = lane >> 2, qd = lane & 3;
    const int qb = blockIdx.x;                       // 0..15 (128-row blocks)
    const int bh = blockIdx.y;
    const int b = bh >> 4, h = bh & 15;
    const int i0 = qb << 7;
    const size_t base = (size_t)b * NN * (3 * CC) + h * DD;

    // shuffle-conversion constants
    const int e = qd & 1;
    const int srcA = (lane & ~3) | (qd >> 1);
    const int srcB = srcA + 2;

    // ---- load Q (scaled by 1/8) ----
    #pragma unroll
    for (int l = 0; l < 8; l++) {
        const int idx = tid + l * 256;
        const int r = idx >> 4, c = (idx & 15) << 2;
        float4 v = *(const float4*)(qkv + base + (size_t)(i0 + r) * (3 * CC) + c);
        uint4 t;
        t.x = f32_to_tf32(v.x * 0.125f); t.y = f32_to_tf32(v.y * 0.125f);
        t.z = f32_to_tf32(v.z * 0.125f); t.w = f32_to_tf32(v.w * 0.125f);
        *(uint4*)&Qs[r * AST + c] = t;
    }

    // ---- K/V loader geometry: 64x64 tile, 4 float4 each per thread ----
    const int lr[4] = { tid >> 4, (tid + 256) >> 4, (tid + 512) >> 4, (tid + 768) >> 4 };
    const int lc = (tid & 15) << 2;

    // prologue: K/V block 0 straight into stage 0
    #pragma unroll
    for (int l = 0; l < 4; l++) {
        const int c = lr[l];
        float4 kv = *(const float4*)(qkv + base + CC + (size_t)c * (3 * CC) + lc);
        uint4 t;
        t.x = f32_to_tf32(kv.x); t.y = f32_to_tf32(kv.y);
        t.z = f32_to_tf32(kv.z); t.w = f32_to_tf32(kv.w);
        *(uint4*)&Ks0[c * AST + lc] = t;
        float4 vv = *(const float4*)(qkv + base + 2 * CC + (size_t)c * (3 * CC) + lc);
        t.x = f32_to_tf32(vv.x); t.y = f32_to_tf32(vv.y);
        t.z = f32_to_tf32(vv.z); t.w = f32_to_tf32(vv.w);
        *(uint4*)&Vs0[c * VST + lc] = t;
    }
    __syncthreads();

    float o[8][4];
    #pragma unroll
    for (int nj = 0; nj < 8; nj++)
        #pragma unroll
        for (int ee = 0; ee < 4; ee++) o[nj][ee] = 0.f;
    float m0 = -1e30f, m1 = -1e30f, l0 = 0.f, l1 = 0.f;

    const int rb = (wid * 16 + g) * AST;
    const int row0 = i0 + wid * 16 + g;
    const int kbmax = 2 * qb + 1;

    for (int kb = 0; kb <= kbmax; kb++) {
        const uint32_t* Ksc = (kb & 1) ? Ks1 : Ks0;
        const uint32_t* Vsc = (kb & 1) ? Vs1 : Vs0;
        uint32_t* Ksn = (kb & 1) ? Ks0 : Ks1;
        uint32_t* Vsn = (kb & 1) ? Vs0 : Vs1;
        const int k0r = kb << 6;
        const bool pref = (kb < kbmax);

        // issue next tile's LDGs early
        float4 kreg[4], vreg[4];
        if (pref) {
            const int nk0 = k0r + 64;
            #pragma unroll
            for (int l = 0; l < 4; l++) {
                kreg[l] = *(const float4*)(qkv + base + CC + (size_t)(nk0 + lr[l]) * (3 * CC) + lc);
                vreg[l] = *(const float4*)(qkv + base + 2 * CC + (size_t)(nk0 + lr[l]) * (3 * CC) + lc);
            }
        }

        // ---- S = Q K^T ----
        float s[8][4];
        #pragma unroll
        for (int nj = 0; nj < 8; nj++)
            #pragma unroll
            for (int ee = 0; ee < 4; ee++) s[nj][ee] = 0.f;

        #pragma unroll
        for (int ks = 0; ks < 8; ks++) {
            const int kc0 = ks * 8 + qd;
            uint32_t af[4];
            af[0] = Qs[rb + kc0];
            af[1] = Qs[rb + 8 * AST + kc0];
            af[2] = Qs[rb + kc0 + 4];
            af[3] = Qs[rb + 8 * AST + kc0 + 4];
            #pragma unroll
            for (int nj = 0; nj < 8; nj++) {
                const int nb = (nj * 8 + g) * AST;
                mma_tf32(s[nj], af, Ksc[nb + kc0], Ksc[nb + kc0 + 4]);
            }
        }

        // causal mask (only when this K block can cross the diagonal)
        if (kb >= 2 * qb) {
            #pragma unroll
            for (int nj = 0; nj < 8; nj++) {
                const int col = k0r + nj * 8 + 2 * qd;
                if (col > row0)     s[nj][0] = -1e30f;
                if (col + 1 > row0) s[nj][1] = -1e30f;
                if (col > row0 + 8)     s[nj][2] = -1e30f;
                if (col + 1 > row0 + 8) s[nj][3] = -1e30f;
            }
        }

        // ---- online softmax ----
        float mx0 = -1e30f, mx1 = -1e30f;
        #pragma unroll
        for (int nj = 0; nj < 8; nj++) {
            mx0 = fmaxf(mx0, fmaxf(s[nj][0], s[nj][1]));
            mx1 = fmaxf(mx1, fmaxf(s[nj][2], s[nj][3]));
        }
        mx0 = fmaxf(mx0, __shfl_xor_sync(0xffffffffu, mx0, 1));
        mx0 = fmaxf(mx0, __shfl_xor_sync(0xffffffffu, mx0, 2));
        mx1 = fmaxf(mx1, __shfl_xor_sync(0xffffffffu, mx1, 1));
        mx1 = fmaxf(mx1, __shfl_xor_sync(0xffffffffu, mx1, 2));

        const float mn0 = fmaxf(m0, mx0), mn1 = fmaxf(m1, mx1);
        const float al0 = __expf(m0 - mn0), al1 = __expf(m1 - mn1);
        m0 = mn0; m1 = mn1;

        float rs0 = 0.f, rs1 = 0.f;
        #pragma unroll
        for (int nj = 0; nj < 8; nj++) {
            s[nj][0] = __expf(s[nj][0] - mn0); rs0 += s[nj][0];
            s[nj][1] = __expf(s[nj][1] - mn0); rs0 += s[nj][1];
            s[nj][2] = __expf(s[nj][2] - mn1); rs1 += s[nj][2];
            s[nj][3] = __expf(s[nj][3] - mn1); rs1 += s[nj][3];
        }
        rs0 += __shfl_xor_sync(0xffffffffu, rs0, 1);
        rs0 += __shfl_xor_sync(0xffffffffu, rs0, 2);
        rs1 += __shfl_xor_sync(0xffffffffu, rs1, 1);
        rs1 += __shfl_xor_sync(0xffffffffu, rs1, 2);
        l0 = l0 * al0 + rs0;
        l1 = l1 * al1 + rs1;

        #pragma unroll
        for (int nj = 0; nj < 8; nj++) {
            o[nj][0] *= al0; o[nj][1] *= al0;
            o[nj][2] *= al1; o[nj][3] *= al1;
        }

        // ---- O += P @ V  (P a-frags built by intra-quad shuffles) ----
        #pragma unroll
        for (int ks = 0; ks < 8; ks++) {
            const float p0a = __shfl_sync(0xffffffffu, s[ks][0], srcA);
            const float p0b = __shfl_sync(0xffffffffu, s[ks][1], srcA);
            const float p1a = __shfl_sync(0xffffffffu, s[ks][2], srcA);
            const float p1b = __shfl_sync(0xffffffffu, s[ks][3], srcA);
            const float p2a = __shfl_sync(0xffffffffu, s[ks][0], srcB);
            const float p2b = __shfl_sync(0xffffffffu, s[ks][1], srcB);
            const float p3a = __shfl_sync(0xffffffffu, s[ks][2], srcB);
            const float p3b = __shfl_sync(0xffffffffu, s[ks][3], srcB);
            uint32_t af[4];
            af[0] = f32_to_tf32(e ? p0b : p0a);
            af[1] = f32_to_tf32(e ? p1b : p1a);
            af[2] = f32_to_tf32(e ? p2b : p2a);
            af[3] = f32_to_tf32(e ? p3b : p3a);
            const int kc0 = ks * 8 + qd;
            #pragma unroll
            for (int nj = 0; nj < 8; nj++) {
                mma_tf32(o[nj], af,
                         Vsc[kc0 * VST + nj * 8 + g],
                         Vsc[(kc0 + 4) * VST + nj * 8 + g]);
            }
        }

        // ---- store next tile into the other stage ----
        if (pref) {
            #pragma unroll
            for (int l = 0; l < 4; l++) {
                const int c = lr[l];
                uint4 t;
                t.x = f32_to_tf32(kreg[l].x); t.y = f32_to_tf32(kreg[l].y);
                t.z = f32_to_tf32(kreg[l].z); t.w = f32_to_tf32(kreg[l].w);
                *(uint4*)&Ksn[c * AST + lc] = t;
                t.x = f32_to_tf32(vreg[l].x); t.y = f32_to_tf32(vreg[l].y);
                t.z = f32_to_tf32(vreg[l].z); t.w = f32_to_tf32(vreg[l].w);
                *(uint4*)&Vsn[c * VST + lc] = t;
            }
        }
        __syncthreads();
    }

    // epilogue
    const float inv0 = 1.f / l0, inv1 = 1.f / l1;
    const int orow = b * NN + row0;
    #pragma unroll
    for (int nj = 0; nj < 8; nj++) {
        const int col = h * DD + nj * 8 + 2 * qd;
        *(float2*)(out + (size_t)orow * CC + col) =
            make_float2(o[nj][0] * inv0, o[nj][1] * inv0);
        *(float2*)(out + (size_t)(orow + 8) * CC + col) =
            make_float2(o[nj][2] * inv1, o[nj][3] * inv1);
    }
}

// ============================================================================
// SwiGLU gate: a = silu(a) * c, in place over a.
// ============================================================================
__global__ __launch_bounds__(256) void glu_kernel(
    float* __restrict__ a, const float* __restrict__ c)
{
    const size_t i = ((size_t)blockIdx.x * 256 + threadIdx.x) * 4;
    float4 v = *(const float4*)(a + i);
    float4 g = *(const float4*)(c + i);
    v.x = v.x * g.x / (1.f + __expf(-v.x));
    v.y = v.y * g.y / (1.f + __expf(-v.y));
    v.z = v.z * g.z / (1.f + __expf(-v.z));
    v.w = v.w * g.w / (1.f + __expf(-v.w));
    *(float4*)(a + i) = v;
}

// ============================================================================
// Launch
// ============================================================================
extern "C" void kernel_launch(void* const* d_in, const int* in_sizes, int n_in,
                              void* d_out, int out_size)
{
    const float* x      = (const float*)d_in[0];
    // d_in[1] = mask (causal tril, hardcoded in attn kernel)
    const float* qkv_w  = (const float*)d_in[2];
    const float* qkv_b  = (const float*)d_in[3];
    const float* proj_w = (const float*)d_in[4];
    const float* proj_b = (const float*)d_in[5];
    const float* ln1_g  = (const float*)d_in[6];
    const float* ln1_b  = (const float*)d_in[7];
    const float* ln2_g  = (const float*)d_in[8];
    const float* ln2_b  = (const float*)d_in[9];
    const float* w1     = (const float*)d_in[10];
    const float* w2     = (const float*)d_in[11];
    const float* w3     = (const float*)d_in[12];
    float* out = (float*)d_out;

    float *h, *qkv, *attn, *x1, *b1, *b3;
    cudaGetSymbolAddress((void**)&h,    g_h);
    cudaGetSymbolAddress((void**)&qkv,  g_qkv);
    cudaGetSymbolAddress((void**)&attn, g_attn);
    cudaGetSymbolAddress((void**)&x1,   g_x1);
    cudaGetSymbolAddress((void**)&b1,   g_g1);
    cudaGetSymbolAddress((void**)&b3,   g_g3);

    cudaFuncSetAttribute(attn_kernel,
                         cudaFuncAttributeMaxDynamicSharedMemorySize, ATT_SMEM);

    // 1. LN1
    ln_kernel<<<MROWS, 256>>>(x, ln1_g, ln1_b, h);
    // 2. qkv = h @ qkv_w^T + qkv_b           [8192, 3072]
    gemm_tc_kernel<<<dim3(3 * CC / 128, MROWS / 128), 256>>>(
        h, qkv_w, qkv_b, nullptr, qkv, MROWS, 3 * CC, CC);
    // 3. causal flash attention (tensor cores, Br=128)
    attn_kernel<<<dim3(NN / 128, BB * HH), 256, ATT_SMEM>>>(qkv, attn);
    // 4. x1 = x + attn @ proj_w^T + proj_b   [8192, 1024]
    gemm_tc_kernel<<<dim3(CC / 128, MROWS / 128), 256>>>(
        attn, proj_w, proj_b, x, x1, MROWS, CC, CC);
    // 5. LN2
    ln_kernel<<<MROWS, 256>>>(x1, ln2_g, ln2_b, h);
    // 6. b1 = h @ w1^T                        [8192, 4096]
    gemm_tc_kernel<<<dim3(FFD / 128, MROWS / 128), 256>>>(
        h, w1, nullptr, nullptr, b1, MROWS, FFD, CC);
    // 7. b3 = h @ w3^T                        [8192, 4096]
    gemm_tc_kernel<<<dim3(FFD / 128, MROWS / 128), 256>>>(
        h, w3, nullptr, nullptr, b3, MROWS, FFD, CC);
    // 8. b1 = silu(b1) * b3
    glu_kernel<<<(MROWS * FFD) / (256 * 4), 256>>>(b1, b3);
    // 9. out = x1 + b1 @ w2^T                 [8192, 1024]
    gemm_tc_kernel<<<dim3(CC / 128, MROWS / 128), 256>>>(
        b1, w2, nullptr, x1, out, MROWS, CC, FFD);
}

// round 9
// speedup vs baseline: 3.2033x; 1.1232x over previous
#include <cuda_runtime.h>
#include <cuda_fp16.h>
#include <math.h>
#include <stdint.h>

// Problem constants
#define BB 4
#define NN 2048
#define CC 1024
#define HH 16
#define DD 64
#define FFD 4096
#define MROWS (BB * NN)   // 8192

// -------------------- scratch (allocation-free: __device__ globals) ---------
__device__ float g_h[MROWS * CC];        // LN output (reused for LN1 and LN2)
__device__ float g_qkv[MROWS * 3 * CC];  // qkv projection
__device__ float g_attn[MROWS * CC];     // attention output (pre-proj)
__device__ float g_x1[MROWS * CC];       // x + attn_proj
__device__ float g_g1[MROWS * FFD];      // h @ w1^T, then gated product
__device__ float g_g3[MROWS * FFD];      // h @ w3^T

// ======================= portable PTX helpers (sm_80+) ======================
__device__ __forceinline__ uint32_t f32_to_tf32(float x) {
    uint32_t u;
    asm("cvt.rna.tf32.f32 %0, %1;" : "=r"(u) : "f"(x));
    return u;
}

__device__ __forceinline__ uint32_t packh2(float lo, float hi) {
    __half2 h = __floats2half2_rn(lo, hi);
    return *(uint32_t*)&h;
}

__device__ __forceinline__ void mma_tf32(
    float* d, const uint32_t* a, uint32_t b0, uint32_t b1)
{
    asm volatile(
        "mma.sync.aligned.m16n8k8.row.col.f32.tf32.tf32.f32 "
        "{%0,%1,%2,%3}, {%4,%5,%6,%7}, {%8,%9}, {%0,%1,%2,%3};"
        : "+f"(d[0]), "+f"(d[1]), "+f"(d[2]), "+f"(d[3])
        : "r"(a[0]), "r"(a[1]), "r"(a[2]), "r"(a[3]), "r"(b0), "r"(b1));
}

__device__ __forceinline__ void mma_f16(
    float* d, const uint32_t* a, uint32_t b0, uint32_t b1)
{
    asm volatile(
        "mma.sync.aligned.m16n8k16.row.col.f32.f16.f16.f32 "
        "{%0,%1,%2,%3}, {%4,%5,%6,%7}, {%8,%9}, {%0,%1,%2,%3};"
        : "+f"(d[0]), "+f"(d[1]), "+f"(d[2]), "+f"(d[3])
        : "r"(a[0]), "r"(a[1]), "r"(a[2]), "r"(a[3]), "r"(b0), "r"(b1));
}

// ============================================================================
// LayerNorm: one row (C=1024) per block, 256 threads, 1 float4/thread.
// ============================================================================
__global__ __launch_bounds__(256) void ln_kernel(
    const float* __restrict__ x, const float* __restrict__ g,
    const float* __restrict__ bta, float* __restrict__ out)
{
    __shared__ float ssum[8], ssq[8];
    const int row = blockIdx.x;
    const int tid = threadIdx.x;

    const float4 v = *(const float4*)(x + (size_t)row * CC + tid * 4);
    float s = v.x + v.y + v.z + v.w;
    float q = v.x * v.x + v.y * v.y + v.z * v.z + v.w * v.w;

    #pragma unroll
    for (int off = 16; off; off >>= 1) {
        s += __shfl_xor_sync(0xffffffffu, s, off);
        q += __shfl_xor_sync(0xffffffffu, q, off);
    }
    if ((tid & 31) == 0) { ssum[tid >> 5] = s; ssq[tid >> 5] = q; }
    __syncthreads();

    float ts = 0.f, tq = 0.f;
    #pragma unroll
    for (int i = 0; i < 8; i++) { ts += ssum[i]; tq += ssq[i]; }

    const float mean = ts * (1.f / (float)CC);
    const float var  = tq * (1.f / (float)CC) - mean * mean;
    const float r    = rsqrtf(var + 1e-6f);

    const float4 gg = *(const float4*)(g + tid * 4);
    const float4 bb = *(const float4*)(bta + tid * 4);
    float4 o;
    o.x = (v.x - mean) * r * gg.x + bb.x;
    o.y = (v.y - mean) * r * gg.y + bb.y;
    o.z = (v.z - mean) * r * gg.z + bb.z;
    o.w = (v.w - mean) * r * gg.w + bb.w;
    *(float4*)(out + (size_t)row * CC + tid * 4) = o;
}

// ============================================================================
// fp16 tensor-core GEMM (NT): C[M,N]=A[M,K]@B[N,K]^T (+bias[N]) (+res[M,N])
// mma.sync.m16n8k16.f16, fp32 accumulate. 128x128 CTA tile, 8 warps.
// K-chunk 32 (16 half2 pair-cols). smem holds packed half2 (uint32), row
// stride 20 uint32 -> all 32 banks distinct for fragment reads.
// LDG->reg double buffer; fp32->fp16 conversion once on the STS path.
// ============================================================================
#define KCH 32
#define STRH 20

__global__ __launch_bounds__(256, 2) void gemm_tc_kernel(
    const float* __restrict__ A, const float* __restrict__ B,
    const float* __restrict__ bias, const float* __restrict__ res,
    float* __restrict__ C, int M, int N, int K)
{
    __shared__ uint32_t smA[2][128 * STRH];
    __shared__ uint32_t smB[2][128 * STRH];

    const int tid = threadIdx.x;
    const int wid = tid >> 5, lane = tid & 31;
    const int g = lane >> 2, qd = lane & 3;
    const int warpR = wid & 3, warpC = wid >> 2;
    const int m0 = blockIdx.y * 128, n0 = blockIdx.x * 128;

    const float* Abase = A + (size_t)m0 * K;
    const float* Bbase = B + (size_t)n0 * K;

    // loader: thread covers row lr, 16 floats (half of the 32-K chunk)
    const int lr = tid >> 1;
    const int fc = (tid & 1) * 16;   // float column base
    const int pc = (tid & 1) * 8;    // pair-col (half2) base in smem

    float acc[2][8][4];
    #pragma unroll
    for (int mi = 0; mi < 2; mi++)
        #pragma unroll
        for (int nj = 0; nj < 8; nj++)
            #pragma unroll
            for (int e = 0; e < 4; e++) acc[mi][nj][e] = 0.f;

    const int nk = K / KCH;

    // prologue: chunk 0 -> stage 0
    float4 av[4], bv[4];
    #pragma unroll
    for (int j = 0; j < 4; j++) {
        av[j] = *(const float4*)(Abase + (size_t)lr * K + fc + 4 * j);
        bv[j] = *(const float4*)(Bbase + (size_t)lr * K + fc + 4 * j);
    }
    {
        uint4 t;
        t.x = packh2(av[0].x, av[0].y); t.y = packh2(av[0].z, av[0].w);
        t.z = packh2(av[1].x, av[1].y); t.w = packh2(av[1].z, av[1].w);
        *(uint4*)&smA[0][lr * STRH + pc] = t;
        t.x = packh2(av[2].x, av[2].y); t.y = packh2(av[2].z, av[2].w);
        t.z = packh2(av[3].x, av[3].y); t.w = packh2(av[3].z, av[3].w);
        *(uint4*)&smA[0][lr * STRH + pc + 4] = t;
        t.x = packh2(bv[0].x, bv[0].y); t.y = packh2(bv[0].z, bv[0].w);
        t.z = packh2(bv[1].x, bv[1].y); t.w = packh2(bv[1].z, bv[1].w);
        *(uint4*)&smB[0][lr * STRH + pc] = t;
        t.x = packh2(bv[2].x, bv[2].y); t.y = packh2(bv[2].z, bv[2].w);
        t.z = packh2(bv[3].x, bv[3].y); t.w = packh2(bv[3].z, bv[3].w);
        *(uint4*)&smB[0][lr * STRH + pc + 4] = t;
    }
    __syncthreads();

    for (int kt = 0; kt < nk; kt++) {
        const int s = kt & 1;
        if (kt + 1 < nk) {
            const int k0 = (kt + 1) * KCH;
            #pragma unroll
            for (int j = 0; j < 4; j++) {
                av[j] = *(const float4*)(Abase + (size_t)lr * K + k0 + fc + 4 * j);
                bv[j] = *(const float4*)(Bbase + (size_t)lr * K + k0 + fc + 4 * j);
            }
        }

        const uint32_t* As = smA[s];
        const uint32_t* Bs = smB[s];
        #pragma unroll
        for (int ks = 0; ks < 2; ks++) {
            const int kc0 = ks * 8 + qd;           // pair-col for k-lo halves
            uint32_t af[2][4];
            #pragma unroll
            for (int mi = 0; mi < 2; mi++) {
                const int rb = (warpR * 32 + mi * 16 + g) * STRH;
                af[mi][0] = As[rb + kc0];                  // a0: row g,   k-lo
                af[mi][1] = As[rb + 8 * STRH + kc0];       // a1: row g+8, k-lo
                af[mi][2] = As[rb + kc0 + 4];              // a2: row g,   k-hi
                af[mi][3] = As[rb + 8 * STRH + kc0 + 4];   // a3: row g+8, k-hi
            }
            #pragma unroll
            for (int nj = 0; nj < 8; nj++) {
                const int nb = (warpC * 64 + nj * 8 + g) * STRH;
                const uint32_t bb0 = Bs[nb + kc0];
                const uint32_t bb1 = Bs[nb + kc0 + 4];
                mma_f16(acc[0][nj], af[0], bb0, bb1);
                mma_f16(acc[1][nj], af[1], bb0, bb1);
            }
        }

        if (kt + 1 < nk) {
            const int d = s ^ 1;
            uint4 t;
            t.x = packh2(av[0].x, av[0].y); t.y = packh2(av[0].z, av[0].w);
            t.z = packh2(av[1].x, av[1].y); t.w = packh2(av[1].z, av[1].w);
            *(uint4*)&smA[d][lr * STRH + pc] = t;
            t.x = packh2(av[2].x, av[2].y); t.y = packh2(av[2].z, av[2].w);
            t.z = packh2(av[3].x, av[3].y); t.w = packh2(av[3].z, av[3].w);
            *(uint4*)&smA[d][lr * STRH + pc + 4] = t;
            t.x = packh2(bv[0].x, bv[0].y); t.y = packh2(bv[0].z, bv[0].w);
            t.z = packh2(bv[1].x, bv[1].y); t.w = packh2(bv[1].z, bv[1].w);
            *(uint4*)&smB[d][lr * STRH + pc] = t;
            t.x = packh2(bv[2].x, bv[2].y); t.y = packh2(bv[2].z, bv[2].w);
            t.z = packh2(bv[3].x, bv[3].y); t.w = packh2(bv[3].z, bv[3].w);
            *(uint4*)&smB[d][lr * STRH + pc + 4] = t;
            __syncthreads();
        }
    }

    // epilogue: c-frag (mi,nj): rows base+{g,g+8}, cols nj*8 + 2qd + {0,1}
    #pragma unroll
    for (int mi = 0; mi < 2; mi++) {
        const int rowa = m0 + warpR * 32 + mi * 16 + g;
        #pragma unroll
        for (int nj = 0; nj < 8; nj++) {
            const int col = n0 + warpC * 64 + nj * 8 + 2 * qd;
            float2 v0 = make_float2(acc[mi][nj][0], acc[mi][nj][1]);
            float2 v1 = make_float2(acc[mi][nj][2], acc[mi][nj][3]);
            if (bias) {
                const float bx = bias[col], by = bias[col + 1];
                v0.x += bx; v0.y += by;
                v1.x += bx; v1.y += by;
            }
            if (res) {
                float2 r0 = *(const float2*)(res + (size_t)rowa * N + col);
                float2 r1 = *(const float2*)(res + (size_t)(rowa + 8) * N + col);
                v0.x += r0.x; v0.y += r0.y;
                v1.x += r1.x; v1.y += r1.y;
            }
            *(float2*)(C + (size_t)rowa * N + col) = v0;
            *(float2*)(C + (size_t)(rowa + 8) * N + col) = v1;
        }
    }
}

// ============================================================================
// Tensor-core flash attention (causal), tf32 MMA + fp32 softmax. (unchanged)
// 256 threads (8 warps). Br=128, Bc=64, D=64.
// ============================================================================
#define AST 68
#define VST 72
#define ATT_SMEM ((128 * AST + 2 * 64 * AST + 2 * 64 * VST) * 4)

__global__ __launch_bounds__(256) void attn_kernel(
    const float* __restrict__ qkv, float* __restrict__ out)
{
    extern __shared__ uint32_t sh[];
    uint32_t* Qs = sh;
    uint32_t* Ks0 = sh + 128 * AST;
    uint32_t* Ks1 = Ks0 + 64 * AST;
    uint32_t* Vs0 = Ks1 + 64 * AST;
    uint32_t* Vs1 = Vs0 + 64 * VST;

    const int tid = threadIdx.x;
    const int wid = tid >> 5, lane = tid & 31;
    const int g = lane >> 2, qd = lane & 3;
    const int qb = blockIdx.x;
    const int bh = blockIdx.y;
    const int b = bh >> 4, h = bh & 15;
    const int i0 = qb << 7;
    const size_t base = (size_t)b * NN * (3 * CC) + h * DD;

    const int e = qd & 1;
    const int srcA = (lane & ~3) | (qd >> 1);
    const int srcB = srcA + 2;

    #pragma unroll
    for (int l = 0; l < 8; l++) {
        const int idx = tid + l * 256;
        const int r = idx >> 4, c = (idx & 15) << 2;
        float4 v = *(const float4*)(qkv + base + (size_t)(i0 + r) * (3 * CC) + c);
        uint4 t;
        t.x = f32_to_tf32(v.x * 0.125f); t.y = f32_to_tf32(v.y * 0.125f);
        t.z = f32_to_tf32(v.z * 0.125f); t.w = f32_to_tf32(v.w * 0.125f);
        *(uint4*)&Qs[r * AST + c] = t;
    }

    const int lr[4] = { tid >> 4, (tid + 256) >> 4, (tid + 512) >> 4, (tid + 768) >> 4 };
    const int lc = (tid & 15) << 2;

    #pragma unroll
    for (int l = 0; l < 4; l++) {
        const int c = lr[l];
        float4 kv = *(const float4*)(qkv + base + CC + (size_t)c * (3 * CC) + lc);
        uint4 t;
        t.x = f32_to_tf32(kv.x); t.y = f32_to_tf32(kv.y);
        t.z = f32_to_tf32(kv.z); t.w = f32_to_tf32(kv.w);
        *(uint4*)&Ks0[c * AST + lc] = t;
        float4 vv = *(const float4*)(qkv + base + 2 * CC + (size_t)c * (3 * CC) + lc);
        t.x = f32_to_tf32(vv.x); t.y = f32_to_tf32(vv.y);
        t.z = f32_to_tf32(vv.z); t.w = f32_to_tf32(vv.w);
        *(uint4*)&Vs0[c * VST + lc] = t;
    }
    __syncthreads();

    float o[8][4];
    #pragma unroll
    for (int nj = 0; nj < 8; nj++)
        #pragma unroll
        for (int ee = 0; ee < 4; ee++) o[nj][ee] = 0.f;
    float m0 = -1e30f, m1 = -1e30f, l0 = 0.f, l1 = 0.f;

    const int rb = (wid * 16 + g) * AST;
    const int row0 = i0 + wid * 16 + g;
    const int kbmax = 2 * qb + 1;

    for (int kb = 0; kb <= kbmax; kb++) {
        const uint32_t* Ksc = (kb & 1) ? Ks1 : Ks0;
        const uint32_t* Vsc = (kb & 1) ? Vs1 : Vs0;
        uint32_t* Ksn = (kb & 1) ? Ks0 : Ks1;
        uint32_t* Vsn = (kb & 1) ? Vs0 : Vs1;
        const int k0r = kb << 6;
        const bool pref = (kb < kbmax);

        float4 kreg[4], vreg[4];
        if (pref) {
            const int nk0 = k0r + 64;
            #pragma unroll
            for (int l = 0; l < 4; l++) {
                kreg[l] = *(const float4*)(qkv + base + CC + (size_t)(nk0 + lr[l]) * (3 * CC) + lc);
                vreg[l] = *(const float4*)(qkv + base + 2 * CC + (size_t)(nk0 + lr[l]) * (3 * CC) + lc);
            }
        }

        float s[8][4];
        #pragma unroll
        for (int nj = 0; nj < 8; nj++)
            #pragma unroll
            for (int ee = 0; ee < 4; ee++) s[nj][ee] = 0.f;

        #pragma unroll
        for (int ks = 0; ks < 8; ks++) {
            const int kc0 = ks * 8 + qd;
            uint32_t af[4];
            af[0] = Qs[rb + kc0];
            af[1] = Qs[rb + 8 * AST + kc0];
            af[2] = Qs[rb + kc0 + 4];
            af[3] = Qs[rb + 8 * AST + kc0 + 4];
            #pragma unroll
            for (int nj = 0; nj < 8; nj++) {
                const int nb = (nj * 8 + g) * AST;
                mma_tf32(s[nj], af, Ksc[nb + kc0], Ksc[nb + kc0 + 4]);
            }
        }

        if (kb >= 2 * qb) {
            #pragma unroll
            for (int nj = 0; nj < 8; nj++) {
                const int col = k0r + nj * 8 + 2 * qd;
                if (col > row0)     s[nj][0] = -1e30f;
                if (col + 1 > row0) s[nj][1] = -1e30f;
                if (col > row0 + 8)     s[nj][2] = -1e30f;
                if (col + 1 > row0 + 8) s[nj][3] = -1e30f;
            }
        }

        float mx0 = -1e30f, mx1 = -1e30f;
        #pragma unroll
        for (int nj = 0; nj < 8; nj++) {
            mx0 = fmaxf(mx0, fmaxf(s[nj][0], s[nj][1]));
            mx1 = fmaxf(mx1, fmaxf(s[nj][2], s[nj][3]));
        }
        mx0 = fmaxf(mx0, __shfl_xor_sync(0xffffffffu, mx0, 1));
        mx0 = fmaxf(mx0, __shfl_xor_sync(0xffffffffu, mx0, 2));
        mx1 = fmaxf(mx1, __shfl_xor_sync(0xffffffffu, mx1, 1));
        mx1 = fmaxf(mx1, __shfl_xor_sync(0xffffffffu, mx1, 2));

        const float mn0 = fmaxf(m0, mx0), mn1 = fmaxf(m1, mx1);
        const float al0 = __expf(m0 - mn0), al1 = __expf(m1 - mn1);
        m0 = mn0; m1 = mn1;

        float rs0 = 0.f, rs1 = 0.f;
        #pragma unroll
        for (int nj = 0; nj < 8; nj++) {
            s[nj][0] = __expf(s[nj][0] - mn0); rs0 += s[nj][0];
            s[nj][1] = __expf(s[nj][1] - mn0); rs0 += s[nj][1];
            s[nj][2] = __expf(s[nj][2] - mn1); rs1 += s[nj][2];
            s[nj][3] = __expf(s[nj][3] - mn1); rs1 += s[nj][3];
        }
        rs0 += __shfl_xor_sync(0xffffffffu, rs0, 1);
        rs0 += __shfl_xor_sync(0xffffffffu, rs0, 2);
        rs1 += __shfl_xor_sync(0xffffffffu, rs1, 1);
        rs1 += __shfl_xor_sync(0xffffffffu, rs1, 2);
        l0 = l0 * al0 + rs0;
        l1 = l1 * al1 + rs1;

        #pragma unroll
        for (int nj = 0; nj < 8; nj++) {
            o[nj][0] *= al0; o[nj][1] *= al0;
            o[nj][2] *= al1; o[nj][3] *= al1;
        }

        #pragma unroll
        for (int ks = 0; ks < 8; ks++) {
            const float p0a = __shfl_sync(0xffffffffu, s[ks][0], srcA);
            const float p0b = __shfl_sync(0xffffffffu, s[ks][1], srcA);
            const float p1a = __shfl_sync(0xffffffffu, s[ks][2], srcA);
            const float p1b = __shfl_sync(0xffffffffu, s[ks][3], srcA);
            const float p2a = __shfl_sync(0xffffffffu, s[ks][0], srcB);
            const float p2b = __shfl_sync(0xffffffffu, s[ks][1], srcB);
            const float p3a = __shfl_sync(0xffffffffu, s[ks][2], srcB);
            const float p3b = __shfl_sync(0xffffffffu, s[ks][3], srcB);
            uint32_t af[4];
            af[0] = f32_to_tf32(e ? p0b : p0a);
            af[1] = f32_to_tf32(e ? p1b : p1a);
            af[2] = f32_to_tf32(e ? p2b : p2a);
            af[3] = f32_to_tf32(e ? p3b : p3a);
            const int kc0 = ks * 8 + qd;
            #pragma unroll
            for (int nj = 0; nj < 8; nj++) {
                mma_tf32(o[nj], af,
                         Vsc[kc0 * VST + nj * 8 + g],
                         Vsc[(kc0 + 4) * VST + nj * 8 + g]);
            }
        }

        if (pref) {
            #pragma unroll
            for (int l = 0; l < 4; l++) {
                const int c = lr[l];
                uint4 t;
                t.x = f32_to_tf32(kreg[l].x); t.y = f32_to_tf32(kreg[l].y);
                t.z = f32_to_tf32(kreg[l].z); t.w = f32_to_tf32(kreg[l].w);
                *(uint4*)&Ksn[c * AST + lc] = t;
                t.x = f32_to_tf32(vreg[l].x); t.y = f32_to_tf32(vreg[l].y);
                t.z = f32_to_tf32(vreg[l].z); t.w = f32_to_tf32(vreg[l].w);
                *(uint4*)&Vsn[c * VST + lc] = t;
            }
        }
        __syncthreads();
    }

    const float inv0 = 1.f / l0, inv1 = 1.f / l1;
    const int orow = b * NN + row0;
    #pragma unroll
    for (int nj = 0; nj < 8; nj++) {
        const int col = h * DD + nj * 8 + 2 * qd;
        *(float2*)(out + (size_t)orow * CC + col) =
            make_float2(o[nj][0] * inv0, o[nj][1] * inv0);
        *(float2*)(out + (size_t)(orow + 8) * CC + col) =
            make_float2(o[nj][2] * inv1, o[nj][3] * inv1);
    }
}

// ============================================================================
// SwiGLU gate: a = silu(a) * c, in place over a.
// ============================================================================
__global__ __launch_bounds__(256) void glu_kernel(
    float* __restrict__ a, const float* __restrict__ c)
{
    const size_t i = ((size_t)blockIdx.x * 256 + threadIdx.x) * 4;
    float4 v = *(const float4*)(a + i);
    float4 g = *(const float4*)(c + i);
    v.x = v.x * g.x / (1.f + __expf(-v.x));
    v.y = v.y * g.y / (1.f + __expf(-v.y));
    v.z = v.z * g.z / (1.f + __expf(-v.z));
    v.w = v.w * g.w / (1.f + __expf(-v.w));
    *(float4*)(a + i) = v;
}

// ============================================================================
// Launch
// ============================================================================
extern "C" void kernel_launch(void* const* d_in, const int* in_sizes, int n_in,
                              void* d_out, int out_size)
{
    const float* x      = (const float*)d_in[0];
    // d_in[1] = mask (causal tril, hardcoded in attn kernel)
    const float* qkv_w  = (const float*)d_in[2];
    const float* qkv_b  = (const float*)d_in[3];
    const float* proj_w = (const float*)d_in[4];
    const float* proj_b = (const float*)d_in[5];
    const float* ln1_g  = (const float*)d_in[6];
    const float* ln1_b  = (const float*)d_in[7];
    const float* ln2_g  = (const float*)d_in[8];
    const float* ln2_b  = (const float*)d_in[9];
    const float* w1     = (const float*)d_in[10];
    const float* w2     = (const float*)d_in[11];
    const float* w3     = (const float*)d_in[12];
    float* out = (float*)d_out;

    float *h, *qkv, *attn, *x1, *b1, *b3;
    cudaGetSymbolAddress((void**)&h,    g_h);
    cudaGetSymbolAddress((void**)&qkv,  g_qkv);
    cudaGetSymbolAddress((void**)&attn, g_attn);
    cudaGetSymbolAddress((void**)&x1,   g_x1);
    cudaGetSymbolAddress((void**)&b1,   g_g1);
    cudaGetSymbolAddress((void**)&b3,   g_g3);

    cudaFuncSetAttribute(attn_kernel,
                         cudaFuncAttributeMaxDynamicSharedMemorySize, ATT_SMEM);

    // 1. LN1
    ln_kernel<<<MROWS, 256>>>(x, ln1_g, ln1_b, h);
    // 2. qkv = h @ qkv_w^T + qkv_b           [8192, 3072]
    gemm_tc_kernel<<<dim3(3 * CC / 128, MROWS / 128), 256>>>(
        h, qkv_w, qkv_b, nullptr, qkv, MROWS, 3 * CC, CC);
    // 3. causal flash attention (tensor cores, Br=128)
    attn_kernel<<<dim3(NN / 128, BB * HH), 256, ATT_SMEM>>>(qkv, attn);
    // 4. x1 = x + attn @ proj_w^T + proj_b   [8192, 1024]
    gemm_tc_kernel<<<dim3(CC / 128, MROWS / 128), 256>>>(
        attn, proj_w, proj_b, x, x1, MROWS, CC, CC);
    // 5. LN2
    ln_kernel<<<MROWS, 256>>>(x1, ln2_g, ln2_b, h);
    // 6. b1 = h @ w1^T                        [8192, 4096]
    gemm_tc_kernel<<<dim3(FFD / 128, MROWS / 128), 256>>>(
        h, w1, nullptr, nullptr, b1, MROWS, FFD, CC);
    // 7. b3 = h @ w3^T                        [8192, 4096]
    gemm_tc_kernel<<<dim3(FFD / 128, MROWS / 128), 256>>>(
        h, w3, nullptr, nullptr, b3, MROWS, FFD, CC);
    // 8. b1 = silu(b1) * b3
    glu_kernel<<<(MROWS * FFD) / (256 * 4), 256>>>(b1, b3);
    // 9. out = x1 + b1 @ w2^T                 [8192, 1024]
    gemm_tc_kernel<<<dim3(CC / 128, MROWS / 128), 256>>>(
        b1, w2, nullptr, x1, out, MROWS, CC, FFD);
}

// round 11
// speedup vs baseline: 4.6504x; 1.4517x over previous
#include <cuda_runtime.h>
#include <cuda_fp16.h>
#include <math.h>
#include <stdint.h>

// Problem constants
#define BB 4
#define NN 2048
#define CC 1024
#define HH 16
#define DD 64
#define FFD 4096
#define MROWS (BB * NN)   // 8192

// -------------------- scratch (allocation-free: __device__ globals) ---------
__device__ __half g_qkvw_h[3 * CC * CC];
__device__ __half g_projw_h[CC * CC];
__device__ __half g_w1_h[FFD * CC];
__device__ __half g_w3_h[FFD * CC];
__device__ __half g_w2_h[CC * FFD];

__device__ __half g_h_h[MROWS * CC];       // LN output (fp16)
__device__ __half g_qkv_h[MROWS * 3 * CC]; // qkv projection (fp16)
__device__ __half g_attn_h[MROWS * CC];    // attention output (fp16)
__device__ float  g_x1[MROWS * CC];        // x + attn_proj (fp32 residual)
__device__ __half g_b1_h[MROWS * FFD];     // h @ w1^T -> gated (fp16)
__device__ __half g_b3_h[MROWS * FFD];     // h @ w3^T (fp16)

// ======================= portable PTX helpers (sm_80+) ======================
__device__ __forceinline__ uint32_t f32_to_tf32(float x) {
    uint32_t u;
    asm("cvt.rna.tf32.f32 %0, %1;" : "=r"(u) : "f"(x));
    return u;
}
__device__ __forceinline__ void cpa16(uint32_t dst, const void* src) {
    asm volatile("cp.async.ca.shared.global [%0], [%1], 16;"
                 :: "r"(dst), "l"(src));
}
#define CPA_COMMIT() asm volatile("cp.async.commit_group;" ::: "memory")
#define CPA_WAIT2()  asm volatile("cp.async.wait_group 2;" ::: "memory")

__device__ __forceinline__ void mma_tf32(
    float* d, const uint32_t* a, uint32_t b0, uint32_t b1)
{
    asm volatile(
        "mma.sync.aligned.m16n8k8.row.col.f32.tf32.tf32.f32 "
        "{%0,%1,%2,%3}, {%4,%5,%6,%7}, {%8,%9}, {%0,%1,%2,%3};"
        : "+f"(d[0]), "+f"(d[1]), "+f"(d[2]), "+f"(d[3])
        : "r"(a[0]), "r"(a[1]), "r"(a[2]), "r"(a[3]), "r"(b0), "r"(b1));
}
__device__ __forceinline__ void mma_f16(
    float* d, const uint32_t* a, uint32_t b0, uint32_t b1)
{
    asm volatile(
        "mma.sync.aligned.m16n8k16.row.col.f32.f16.f16.f32 "
        "{%0,%1,%2,%3}, {%4,%5,%6,%7}, {%8,%9}, {%0,%1,%2,%3};"
        : "+f"(d[0]), "+f"(d[1]), "+f"(d[2]), "+f"(d[3])
        : "r"(a[0]), "r"(a[1]), "r"(a[2]), "r"(a[3]), "r"(b0), "r"(b1));
}

// ============================================================================
// fp32 -> fp16 conversion (weights), 4 elems/thread.
// ============================================================================
__global__ __launch_bounds__(256) void f2h_kernel(
    const float* __restrict__ src, __half* __restrict__ dst)
{
    const size_t i = ((size_t)blockIdx.x * 256 + threadIdx.x) * 4;
    float4 v = *(const float4*)(src + i);
    __half2 h0 = __floats2half2_rn(v.x, v.y);
    __half2 h1 = __floats2half2_rn(v.z, v.w);
    uint2 o;
    o.x = *(uint32_t*)&h0; o.y = *(uint32_t*)&h1;
    *(uint2*)(dst + i) = o;
}

// ============================================================================
// LayerNorm: fp32 in, fp16 out. One row per block, 256 threads.
// ============================================================================
__global__ __launch_bounds__(256) void ln_kernel(
    const float* __restrict__ x, const float* __restrict__ g,
    const float* __restrict__ bta, __half* __restrict__ out)
{
    __shared__ float ssum[8], ssq[8];
    const int row = blockIdx.x;
    const int tid = threadIdx.x;

    const float4 v = *(const float4*)(x + (size_t)row * CC + tid * 4);
    float s = v.x + v.y + v.z + v.w;
    float q = v.x * v.x + v.y * v.y + v.z * v.z + v.w * v.w;

    #pragma unroll
    for (int off = 16; off; off >>= 1) {
        s += __shfl_xor_sync(0xffffffffu, s, off);
        q += __shfl_xor_sync(0xffffffffu, q, off);
    }
    if ((tid & 31) == 0) { ssum[tid >> 5] = s; ssq[tid >> 5] = q; }
    __syncthreads();

    float ts = 0.f, tq = 0.f;
    #pragma unroll
    for (int i = 0; i < 8; i++) { ts += ssum[i]; tq += ssq[i]; }

    const float mean = ts * (1.f / (float)CC);
    const float var  = tq * (1.f / (float)CC) - mean * mean;
    const float r    = rsqrtf(var + 1e-6f);

    const float4 gg = *(const float4*)(g + tid * 4);
    const float4 bb = *(const float4*)(bta + tid * 4);
    __half2 h0 = __floats2half2_rn((v.x - mean) * r * gg.x + bb.x,
                                   (v.y - mean) * r * gg.y + bb.y);
    __half2 h1 = __floats2half2_rn((v.z - mean) * r * gg.z + bb.z,
                                   (v.w - mean) * r * gg.w + bb.w);
    uint2 o;
    o.x = *(uint32_t*)&h0; o.y = *(uint32_t*)&h1;
    *(uint2*)(out + (size_t)row * CC + tid * 4) = o;
}

// ============================================================================
// fp16 tensor-core GEMM (NT), cp.async 4-stage pipeline.
// C[M,N] = A[M,K] @ B[N,K]^T (+bias) (+res). A,B fp16; out fp32 C or fp16 Ch.
// 128x128 CTA tile, 8 warps, K-chunk 32 halves. smem stride 20 uint32/row.
// ============================================================================
#define STRH 20
#define STG_U32 (128 * STRH)            // uint32 per matrix per stage
#define GEMM_SMEM (4 * 2 * STG_U32 * 4) // 4 stages * (A+B) * 4 B = 81920

__global__ __launch_bounds__(256) void gemm_h_kernel(
    const __half* __restrict__ A, const __half* __restrict__ B,
    const float* __restrict__ bias, const float* __restrict__ res,
    float* __restrict__ C, __half* __restrict__ Ch, int M, int N, int K)
{
    extern __shared__ uint32_t sm[];

    const int tid = threadIdx.x;
    const int wid = tid >> 5, lane = tid & 31;
    const int g = lane >> 2, qd = lane & 3;
    const int warpR = wid & 3, warpC = wid >> 2;
    const int m0 = blockIdx.y * 128, n0 = blockIdx.x * 128;

    const __half* Abase = A + (size_t)m0 * K;
    const __half* Bbase = B + (size_t)n0 * K;

    // loader: 2 threads per row; each thread 2x 16B chunks (16 halves)
    const int lr = tid >> 1;
    const int hsel = tid & 1;
    const size_t asrc = (size_t)lr * K + hsel * 16;
    const size_t bsrc = (size_t)lr * K + hsel * 16;
    const uint32_t sbase = (uint32_t)__cvta_generic_to_shared(sm);
    const uint32_t dstoff = (uint32_t)(lr * STRH + hsel * 8) * 4;

    float acc[2][8][4];
    #pragma unroll
    for (int mi = 0; mi < 2; mi++)
        #pragma unroll
        for (int nj = 0; nj < 8; nj++)
            #pragma unroll
            for (int e = 0; e < 4; e++) acc[mi][nj][e] = 0.f;

    const int nk = K >> 5;  // K / 32

    // prologue: stages 0..2
    #pragma unroll
    for (int p = 0; p < 3; p++) {
        const uint32_t sa = sbase + (uint32_t)(2 * p) * (STG_U32 * 4) + dstoff;
        const uint32_t sb = sa + STG_U32 * 4;
        const int k0 = p * 32;
        cpa16(sa,      Abase + asrc + k0);
        cpa16(sa + 16, Abase + asrc + k0 + 8);
        cpa16(sb,      Bbase + bsrc + k0);
        cpa16(sb + 16, Bbase + bsrc + k0 + 8);
        CPA_COMMIT();
    }

    for (int kt = 0; kt < nk; kt++) {
        CPA_WAIT2();
        __syncthreads();

        const uint32_t* As = sm + (size_t)(2 * (kt & 3)) * STG_U32;
        const uint32_t* Bs = As + STG_U32;
        #pragma unroll
        for (int ks = 0; ks < 2; ks++) {
            const int kc0 = ks * 8 + qd;
            uint32_t af[2][4];
            #pragma unroll
            for (int mi = 0; mi < 2; mi++) {
                const int rb = (warpR * 32 + mi * 16 + g) * STRH;
                af[mi][0] = As[rb + kc0];
                af[mi][1] = As[rb + 8 * STRH + kc0];
                af[mi][2] = As[rb + kc0 + 4];
                af[mi][3] = As[rb + 8 * STRH + kc0 + 4];
            }
            #pragma unroll
            for (int nj = 0; nj < 8; nj++) {
                const int nb = (warpC * 64 + nj * 8 + g) * STRH;
                const uint32_t bb0 = Bs[nb + kc0];
                const uint32_t bb1 = Bs[nb + kc0 + 4];
                mma_f16(acc[0][nj], af[0], bb0, bb1);
                mma_f16(acc[1][nj], af[1], bb0, bb1);
            }
        }

        if (kt + 3 < nk) {
            const int p = (kt + 3) & 3;
            const uint32_t sa = sbase + (uint32_t)(2 * p) * (STG_U32 * 4) + dstoff;
            const uint32_t sb = sa + STG_U32 * 4;
            const int k0 = (kt + 3) * 32;
            cpa16(sa,      Abase + asrc + k0);
            cpa16(sa + 16, Abase + asrc + k0 + 8);
            cpa16(sb,      Bbase + bsrc + k0);
            cpa16(sb + 16, Bbase + bsrc + k0 + 8);
        }
        CPA_COMMIT();
    }

    // epilogue
    #pragma unroll
    for (int mi = 0; mi < 2; mi++) {
        const int rowa = m0 + warpR * 32 + mi * 16 + g;
        #pragma unroll
        for (int nj = 0; nj < 8; nj++) {
            const int col = n0 + warpC * 64 + nj * 8 + 2 * qd;
            float2 v0 = make_float2(acc[mi][nj][0], acc[mi][nj][1]);
            float2 v1 = make_float2(acc[mi][nj][2], acc[mi][nj][3]);
            if (bias) {
                const float bx = bias[col], by = bias[col + 1];
                v0.x += bx; v0.y += by;
                v1.x += bx; v1.y += by;
            }
            if (res) {
                float2 r0 = *(const float2*)(res + (size_t)rowa * N + col);
                float2 r1 = *(const float2*)(res + (size_t)(rowa + 8) * N + col);
                v0.x += r0.x; v0.y += r0.y;
                v1.x += r1.x; v1.y += r1.y;
            }
            if (C) {
                *(float2*)(C + (size_t)rowa * N + col) = v0;
                *(float2*)(C + (size_t)(rowa + 8) * N + col) = v1;
            } else {
                __half2 h0 = __floats2half2_rn(v0.x, v0.y);
                __half2 h1 = __floats2half2_rn(v1.x, v1.y);
                *(__half2*)(Ch + (size_t)rowa * N + col) = h0;
                *(__half2*)(Ch + (size_t)(rowa + 8) * N + col) = h1;
            }
        }
    }
}

// ============================================================================
// Tensor-core flash attention (causal), tf32 MMA + fp32 softmax.
// fp16 qkv input, fp16 output. 256 threads, Br=128, Bc=64, D=64.
// ============================================================================
#define AST 68
#define VST 72
#define ATT_SMEM ((128 * AST + 2 * 64 * AST + 2 * 64 * VST) * 4)

__global__ __launch_bounds__(256) void attn_kernel(
    const __half* __restrict__ qkv, __half* __restrict__ out)
{
    extern __shared__ uint32_t sh[];
    uint32_t* Qs = sh;
    uint32_t* Ks0 = sh + 128 * AST;
    uint32_t* Ks1 = Ks0 + 64 * AST;
    uint32_t* Vs0 = Ks1 + 64 * AST;
    uint32_t* Vs1 = Vs0 + 64 * VST;

    const int tid = threadIdx.x;
    const int wid = tid >> 5, lane = tid & 31;
    const int g = lane >> 2, qd = lane & 3;
    const int qb = blockIdx.x;
    const int bh = blockIdx.y;
    const int b = bh >> 4, h = bh & 15;
    const int i0 = qb << 7;
    const size_t base = (size_t)b * NN * (3 * CC) + h * DD;

    const int e = qd & 1;
    const int srcA = (lane & ~3) | (qd >> 1);
    const int srcB = srcA + 2;

    // load Q (scaled by 1/8)
    #pragma unroll
    for (int l = 0; l < 8; l++) {
        const int idx = tid + l * 256;
        const int r = idx >> 4, c = (idx & 15) << 2;
        uint2 raw = *(const uint2*)(qkv + base + (size_t)(i0 + r) * (3 * CC) + c);
        float2 f0 = __half22float2(*(__half2*)&raw.x);
        float2 f1 = __half22float2(*(__half2*)&raw.y);
        uint4 t;
        t.x = f32_to_tf32(f0.x * 0.125f); t.y = f32_to_tf32(f0.y * 0.125f);
        t.z = f32_to_tf32(f1.x * 0.125f); t.w = f32_to_tf32(f1.y * 0.125f);
        *(uint4*)&Qs[r * AST + c] = t;
    }

    const int lr[4] = { tid >> 4, (tid + 256) >> 4, (tid + 512) >> 4, (tid + 768) >> 4 };
    const int lc = (tid & 15) << 2;

    // prologue: K/V block 0 -> stage 0
    #pragma unroll
    for (int l = 0; l < 4; l++) {
        const int c = lr[l];
        uint2 kraw = *(const uint2*)(qkv + base + CC + (size_t)c * (3 * CC) + lc);
        float2 f0 = __half22float2(*(__half2*)&kraw.x);
        float2 f1 = __half22float2(*(__half2*)&kraw.y);
        uint4 t;
        t.x = f32_to_tf32(f0.x); t.y = f32_to_tf32(f0.y);
        t.z = f32_to_tf32(f1.x); t.w = f32_to_tf32(f1.y);
        *(uint4*)&Ks0[c * AST + lc] = t;
        uint2 vraw = *(const uint2*)(qkv + base + 2 * CC + (size_t)c * (3 * CC) + lc);
        f0 = __half22float2(*(__half2*)&vraw.x);
        f1 = __half22float2(*(__half2*)&vraw.y);
        t.x = f32_to_tf32(f0.x); t.y = f32_to_tf32(f0.y);
        t.z = f32_to_tf32(f1.x); t.w = f32_to_tf32(f1.y);
        *(uint4*)&Vs0[c * VST + lc] = t;
    }
    __syncthreads();

    float o[8][4];
    #pragma unroll
    for (int nj = 0; nj < 8; nj++)
        #pragma unroll
        for (int ee = 0; ee < 4; ee++) o[nj][ee] = 0.f;
    float m0 = -1e30f, m1 = -1e30f, l0 = 0.f, l1 = 0.f;

    const int rb = (wid * 16 + g) * AST;
    const int row0 = i0 + wid * 16 + g;
    const int kbmax = 2 * qb + 1;

    for (int kb = 0; kb <= kbmax; kb++) {
        const uint32_t* Ksc = (kb & 1) ? Ks1 : Ks0;
        const uint32_t* Vsc = (kb & 1) ? Vs1 : Vs0;
        uint32_t* Ksn = (kb & 1) ? Ks0 : Ks1;
        uint32_t* Vsn = (kb & 1) ? Vs0 : Vs1;
        const int k0r = kb << 6;
        const bool pref = (kb < kbmax);

        uint2 kreg[4], vreg[4];
        if (pref) {
            const int nk0 = k0r + 64;
            #pragma unroll
            for (int l = 0; l < 4; l++) {
                kreg[l] = *(const uint2*)(qkv + base + CC + (size_t)(nk0 + lr[l]) * (3 * CC) + lc);
                vreg[l] = *(const uint2*)(qkv + base + 2 * CC + (size_t)(nk0 + lr[l]) * (3 * CC) + lc);
            }
        }

        float s[8][4];
        #pragma unroll
        for (int nj = 0; nj < 8; nj++)
            #pragma unroll
            for (int ee = 0; ee < 4; ee++) s[nj][ee] = 0.f;

        #pragma unroll
        for (int ks = 0; ks < 8; ks++) {
            const int kc0 = ks * 8 + qd;
            uint32_t af[4];
            af[0] = Qs[rb + kc0];
            af[1] = Qs[rb + 8 * AST + kc0];
            af[2] = Qs[rb + kc0 + 4];
            af[3] = Qs[rb + 8 * AST + kc0 + 4];
            #pragma unroll
            for (int nj = 0; nj < 8; nj++) {
                const int nb = (nj * 8 + g) * AST;
                mma_tf32(s[nj], af, Ksc[nb + kc0], Ksc[nb + kc0 + 4]);
            }
        }

        if (kb >= 2 * qb) {
            #pragma unroll
            for (int nj = 0; nj < 8; nj++) {
                const int col = k0r + nj * 8 + 2 * qd;
                if (col > row0)     s[nj][0] = -1e30f;
                if (col + 1 > row0) s[nj][1] = -1e30f;
                if (col > row0 + 8)     s[nj][2] = -1e30f;
                if (col + 1 > row0 + 8) s[nj][3] = -1e30f;
            }
        }

        float mx0 = -1e30f, mx1 = -1e30f;
        #pragma unroll
        for (int nj = 0; nj < 8; nj++) {
            mx0 = fmaxf(mx0, fmaxf(s[nj][0], s[nj][1]));
            mx1 = fmaxf(mx1, fmaxf(s[nj][2], s[nj][3]));
        }
        mx0 = fmaxf(mx0, __shfl_xor_sync(0xffffffffu, mx0, 1));
        mx0 = fmaxf(mx0, __shfl_xor_sync(0xffffffffu, mx0, 2));
        mx1 = fmaxf(mx1, __shfl_xor_sync(0xffffffffu, mx1, 1));
        mx1 = fmaxf(mx1, __shfl_xor_sync(0xffffffffu, mx1, 2));

        const float mn0 = fmaxf(m0, mx0), mn1 = fmaxf(m1, mx1);
        const float al0 = __expf(m0 - mn0), al1 = __expf(m1 - mn1);
        m0 = mn0; m1 = mn1;

        float rs0 = 0.f, rs1 = 0.f;
        #pragma unroll
        for (int nj = 0; nj < 8; nj++) {
            s[nj][0] = __expf(s[nj][0] - mn0); rs0 += s[nj][0];
            s[nj][1] = __expf(s[nj][1] - mn0); rs0 += s[nj][1];
            s[nj][2] = __expf(s[nj][2] - mn1); rs1 += s[nj][2];
            s[nj][3] = __expf(s[nj][3] - mn1); rs1 += s[nj][3];
        }
        rs0 += __shfl_xor_sync(0xffffffffu, rs0, 1);
        rs0 += __shfl_xor_sync(0xffffffffu, rs0, 2);
        rs1 += __shfl_xor_sync(0xffffffffu, rs1, 1);
        rs1 += __shfl_xor_sync(0xffffffffu, rs1, 2);
        l0 = l0 * al0 + rs0;
        l1 = l1 * al1 + rs1;

        #pragma unroll
        for (int nj = 0; nj < 8; nj++) {
            o[nj][0] *= al0; o[nj][1] *= al0;
            o[nj][2] *= al1; o[nj][3] *= al1;
        }

        #pragma unroll
        for (int ks = 0; ks < 8; ks++) {
            const float p0a = __shfl_sync(0xffffffffu, s[ks][0], srcA);
            const float p0b = __shfl_sync(0xffffffffu, s[ks][1], srcA);
            const float p1a = __shfl_sync(0xffffffffu, s[ks][2], srcA);
            const float p1b = __shfl_sync(0xffffffffu, s[ks][3], srcA);
            const float p2a = __shfl_sync(0xffffffffu, s[ks][0], srcB);
            const float p2b = __shfl_sync(0xffffffffu, s[ks][1], srcB);
            const float p3a = __shfl_sync(0xffffffffu, s[ks][2], srcB);
            const float p3b = __shfl_sync(0xffffffffu, s[ks][3], srcB);
            uint32_t af[4];
            af[0] = f32_to_tf32(e ? p0b : p0a);
            af[1] = f32_to_tf32(e ? p1b : p1a);
            af[2] = f32_to_tf32(e ? p2b : p2a);
            af[3] = f32_to_tf32(e ? p3b : p3a);
            const int kc0 = ks * 8 + qd;
            #pragma unroll
            for (int nj = 0; nj < 8; nj++) {
                mma_tf32(o[nj], af,
                         Vsc[kc0 * VST + nj * 8 + g],
                         Vsc[(kc0 + 4) * VST + nj * 8 + g]);
            }
        }

        if (pref) {
            #pragma unroll
            for (int l = 0; l < 4; l++) {
                const int c = lr[l];
                float2 f0 = __half22float2(*(__half2*)&kreg[l].x);
                float2 f1 = __half22float2(*(__half2*)&kreg[l].y);
                uint4 t;
                t.x = f32_to_tf32(f0.x); t.y = f32_to_tf32(f0.y);
                t.z = f32_to_tf32(f1.x); t.w = f32_to_tf32(f1.y);
                *(uint4*)&Ksn[c * AST + lc] = t;
                f0 = __half22float2(*(__half2*)&vreg[l].x);
                f1 = __half22float2(*(__half2*)&vreg[l].y);
                t.x = f32_to_tf32(f0.x); t.y = f32_to_tf32(f0.y);
                t.z = f32_to_tf32(f1.x); t.w = f32_to_tf32(f1.y);
                *(uint4*)&Vsn[c * VST + lc] = t;
            }
        }
        __syncthreads();
    }

    const float inv0 = 1.f / l0, inv1 = 1.f / l1;
    const int orow = b * NN + row0;
    #pragma unroll
    for (int nj = 0; nj < 8; nj++) {
        const int col = h * DD + nj * 8 + 2 * qd;
        __half2 h0 = __floats2half2_rn(o[nj][0] * inv0, o[nj][1] * inv0);
        __half2 h1 = __floats2half2_rn(o[nj][2] * inv1, o[nj][3] * inv1);
        *(__half2*)(out + (size_t)orow * CC + col) = h0;
        *(__half2*)(out + (size_t)(orow + 8) * CC + col) = h1;
    }
}

// ============================================================================
// SwiGLU gate (fp16): a = silu(a) * c, in place over a.
// ============================================================================
__global__ __launch_bounds__(256) void glu_kernel(
    __half* __restrict__ a, const __half* __restrict__ c)
{
    const size_t i = ((size_t)blockIdx.x * 256 + threadIdx.x) * 4;
    uint2 ar = *(const uint2*)(a + i);
    uint2 cr = *(const uint2*)(c + i);
    float2 a0 = __half22float2(*(__half2*)&ar.x);
    float2 a1 = __half22float2(*(__half2*)&ar.y);
    float2 c0 = __half22float2(*(__half2*)&cr.x);
    float2 c1 = __half22float2(*(__half2*)&cr.y);
    a0.x = a0.x * c0.x / (1.f + __expf(-a0.x));
    a0.y = a0.y * c0.y / (1.f + __expf(-a0.y));
    a1.x = a1.x * c1.x / (1.f + __expf(-a1.x));
    a1.y = a1.y * c1.y / (1.f + __expf(-a1.y));
    __half2 h0 = __floats2half2_rn(a0.x, a0.y);
    __half2 h1 = __floats2half2_rn(a1.x, a1.y);
    uint2 o;
    o.x = *(uint32_t*)&h0; o.y = *(uint32_t*)&h1;
    *(uint2*)(a + i) = o;
}

// ============================================================================
// Launch
// ============================================================================
extern "C" void kernel_launch(void* const* d_in, const int* in_sizes, int n_in,
                              void* d_out, int out_size)
{
    const float* x      = (const float*)d_in[0];
    // d_in[1] = mask (causal tril, hardcoded in attn kernel)
    const float* qkv_w  = (const float*)d_in[2];
    const float* qkv_b  = (const float*)d_in[3];
    const float* proj_w = (const float*)d_in[4];
    const float* proj_b = (const float*)d_in[5];
    const float* ln1_g  = (const float*)d_in[6];
    const float* ln1_b  = (const float*)d_in[7];
    const float* ln2_g  = (const float*)d_in[8];
    const float* ln2_b  = (const float*)d_in[9];
    const float* w1     = (const float*)d_in[10];
    const float* w2     = (const float*)d_in[11];
    const float* w3     = (const float*)d_in[12];
    float* out = (float*)d_out;

    __half *qkvw_h, *projw_h, *w1_h, *w3_h, *w2_h;
    __half *hh, *qkvh, *attnh, *b1h, *b3h;
    float* x1;
    cudaGetSymbolAddress((void**)&qkvw_h, g_qkvw_h);
    cudaGetSymbolAddress((void**)&projw_h, g_projw_h);
    cudaGetSymbolAddress((void**)&w1_h, g_w1_h);
    cudaGetSymbolAddress((void**)&w3_h, g_w3_h);
    cudaGetSymbolAddress((void**)&w2_h, g_w2_h);
    cudaGetSymbolAddress((void**)&hh,   g_h_h);
    cudaGetSymbolAddress((void**)&qkvh, g_qkv_h);
    cudaGetSymbolAddress((void**)&attnh, g_attn_h);
    cudaGetSymbolAddress((void**)&x1,   g_x1);
    cudaGetSymbolAddress((void**)&b1h,  g_b1_h);
    cudaGetSymbolAddress((void**)&b3h,  g_b3_h);

    cudaFuncSetAttribute(attn_kernel,
                         cudaFuncAttributeMaxDynamicSharedMemorySize, ATT_SMEM);
    cudaFuncSetAttribute(gemm_h_kernel,
                         cudaFuncAttributeMaxDynamicSharedMemorySize, GEMM_SMEM);

    // 0. weights -> fp16
    f2h_kernel<<<(3 * CC * CC) / 1024, 256>>>(qkv_w, qkvw_h);
    f2h_kernel<<<(CC * CC) / 1024, 256>>>(proj_w, projw_h);
    f2h_kernel<<<(FFD * CC) / 1024, 256>>>(w1, w1_h);
    f2h_kernel<<<(FFD * CC) / 1024, 256>>>(w3, w3_h);
    f2h_kernel<<<(CC * FFD) / 1024, 256>>>(w2, w2_h);

    // 1. LN1 (fp16 out)
    ln_kernel<<<MROWS, 256>>>(x, ln1_g, ln1_b, hh);
    // 2. qkv = h @ qkv_w^T + qkv_b -> fp16   [8192, 3072]
    gemm_h_kernel<<<dim3(3 * CC / 128, MROWS / 128), 256, GEMM_SMEM>>>(
        hh, qkvw_h, qkv_b, nullptr, nullptr, qkvh, MROWS, 3 * CC, CC);
    // 3. causal flash attention -> fp16
    attn_kernel<<<dim3(NN / 128, BB * HH), 256, ATT_SMEM>>>(qkvh, attnh);
    // 4. x1 = x + attn @ proj_w^T + proj_b -> fp32
    gemm_h_kernel<<<dim3(CC / 128, MROWS / 128), 256, GEMM_SMEM>>>(
        attnh, projw_h, proj_b, x, x1, nullptr, MROWS, CC, CC);
    // 5. LN2 (fp16 out)
    ln_kernel<<<MROWS, 256>>>(x1, ln2_g, ln2_b, hh);
    // 6. b1 = h @ w1^T -> fp16               [8192, 4096]
    gemm_h_kernel<<<dim3(FFD / 128, MROWS / 128), 256, GEMM_SMEM>>>(
        hh, w1_h, nullptr, nullptr, nullptr, b1h, MROWS, FFD, CC);
    // 7. b3 = h @ w3^T -> fp16               [8192, 4096]
    gemm_h_kernel<<<dim3(FFD / 128, MROWS / 128), 256, GEMM_SMEM>>>(
        hh, w3_h, nullptr, nullptr, nullptr, b3h, MROWS, FFD, CC);
    // 8. b1 = silu(b1) * b3 (fp16)
    glu_kernel<<<(MROWS * FFD) / (256 * 4), 256>>>(b1h, b3h);
    // 9. out = x1 + b1 @ w2^T -> fp32        [8192, 1024]
    gemm_h_kernel<<<dim3(CC / 128, MROWS / 128), 256, GEMM_SMEM>>>(
        b1h, w2_h, nullptr, x1, out, nullptr, MROWS, CC, FFD);
}

// round 13
// speedup vs baseline: 5.3931x; 1.1597x over previous
#include <cuda_runtime.h>
#include <cuda_fp16.h>
#include <math.h>
#include <stdint.h>

// Problem constants
#define BB 4
#define NN 2048
#define CC 1024
#define HH 16
#define DD 64
#define FFD 4096
#define MROWS (BB * NN)   // 8192

// -------------------- scratch (allocation-free: __device__ globals) ---------
__device__ __half g_qkvw_h[3 * CC * CC];
__device__ __half g_projw_h[CC * CC];
__device__ __half g_w13_h[2 * FFD * CC];   // [w1 ; w3] stacked
__device__ __half g_w2_h[CC * FFD];

__device__ __half g_h_h[MROWS * CC];       // LN output (fp16)
__device__ __half g_qkv_h[MROWS * 3 * CC]; // qkv projection (fp16)
__device__ __half g_attn_h[MROWS * CC];    // attention output (fp16)
__device__ float  g_x1[MROWS * CC];        // x + attn_proj (fp32 residual)
__device__ __half g_b13_h[MROWS * 2 * FFD];// [h@w1^T ; h@w3^T] (fp16)
__device__ __half g_b1_h[MROWS * FFD];     // silu(b1)*b3 (fp16)

// ======================= portable PTX helpers (sm_80+) ======================
__device__ __forceinline__ uint32_t f32_to_tf32(float x) {
    uint32_t u;
    asm("cvt.rna.tf32.f32 %0, %1;" : "=r"(u) : "f"(x));
    return u;
}
__device__ __forceinline__ void cpa16(uint32_t dst, const void* src) {
    asm volatile("cp.async.ca.shared.global [%0], [%1], 16;"
                 :: "r"(dst), "l"(src));
}
#define CPA_COMMIT() asm volatile("cp.async.commit_group;" ::: "memory")
#define CPA_WAIT2()  asm volatile("cp.async.wait_group 2;" ::: "memory")

__device__ __forceinline__ void ldsm_x4(
    uint32_t& r0, uint32_t& r1, uint32_t& r2, uint32_t& r3, uint32_t addr)
{
    asm volatile("ldmatrix.sync.aligned.m8n8.x4.shared.b16 {%0,%1,%2,%3}, [%4];"
                 : "=r"(r0), "=r"(r1), "=r"(r2), "=r"(r3) : "r"(addr));
}

__device__ __forceinline__ void mma_tf32(
    float* d, const uint32_t* a, uint32_t b0, uint32_t b1)
{
    asm volatile(
        "mma.sync.aligned.m16n8k8.row.col.f32.tf32.tf32.f32 "
        "{%0,%1,%2,%3}, {%4,%5,%6,%7}, {%8,%9}, {%0,%1,%2,%3};"
        : "+f"(d[0]), "+f"(d[1]), "+f"(d[2]), "+f"(d[3])
        : "r"(a[0]), "r"(a[1]), "r"(a[2]), "r"(a[3]), "r"(b0), "r"(b1));
}
__device__ __forceinline__ void mma_f16(
    float* d, const uint32_t* a, uint32_t b0, uint32_t b1)
{
    asm volatile(
        "mma.sync.aligned.m16n8k16.row.col.f32.f16.f16.f32 "
        "{%0,%1,%2,%3}, {%4,%5,%6,%7}, {%8,%9}, {%0,%1,%2,%3};"
        : "+f"(d[0]), "+f"(d[1]), "+f"(d[2]), "+f"(d[3])
        : "r"(a[0]), "r"(a[1]), "r"(a[2]), "r"(a[3]), "r"(b0), "r"(b1));
}

// ============================================================================
// fp32 -> fp16 conversion (weights), 4 elems/thread.
// ============================================================================
__global__ __launch_bounds__(256) void f2h_kernel(
    const float* __restrict__ src, __half* __restrict__ dst)
{
    const size_t i = ((size_t)blockIdx.x * 256 + threadIdx.x) * 4;
    float4 v = *(const float4*)(src + i);
    __half2 h0 = __floats2half2_rn(v.x, v.y);
    __half2 h1 = __floats2half2_rn(v.z, v.w);
    uint2 o;
    o.x = *(uint32_t*)&h0; o.y = *(uint32_t*)&h1;
    *(uint2*)(dst + i) = o;
}

// ============================================================================
// LayerNorm: fp32 in, fp16 out. One row per block, 256 threads.
// ============================================================================
__global__ __launch_bounds__(256) void ln_kernel(
    const float* __restrict__ x, const float* __restrict__ g,
    const float* __restrict__ bta, __half* __restrict__ out)
{
    __shared__ float ssum[8], ssq[8];
    const int row = blockIdx.x;
    const int tid = threadIdx.x;

    const float4 v = *(const float4*)(x + (size_t)row * CC + tid * 4);
    float s = v.x + v.y + v.z + v.w;
    float q = v.x * v.x + v.y * v.y + v.z * v.z + v.w * v.w;

    #pragma unroll
    for (int off = 16; off; off >>= 1) {
        s += __shfl_xor_sync(0xffffffffu, s, off);
        q += __shfl_xor_sync(0xffffffffu, q, off);
    }
    if ((tid & 31) == 0) { ssum[tid >> 5] = s; ssq[tid >> 5] = q; }
    __syncthreads();

    float ts = 0.f, tq = 0.f;
    #pragma unroll
    for (int i = 0; i < 8; i++) { ts += ssum[i]; tq += ssq[i]; }

    const float mean = ts * (1.f / (float)CC);
    const float var  = tq * (1.f / (float)CC) - mean * mean;
    const float r    = rsqrtf(var + 1e-6f);

    const float4 gg = *(const float4*)(g + tid * 4);
    const float4 bb = *(const float4*)(bta + tid * 4);
    __half2 h0 = __floats2half2_rn((v.x - mean) * r * gg.x + bb.x,
                                   (v.y - mean) * r * gg.y + bb.y);
    __half2 h1 = __floats2half2_rn((v.z - mean) * r * gg.z + bb.z,
                                   (v.w - mean) * r * gg.w + bb.w);
    uint2 o;
    o.x = *(uint32_t*)&h0; o.y = *(uint32_t*)&h1;
    *(uint2*)(out + (size_t)row * CC + tid * 4) = o;
}

// ============================================================================
// fp16 tensor-core GEMM (NT), cp.async 4-stage pipeline + ldmatrix fragments.
// C[M,N] = A[M,K] @ B[N,K]^T (+bias) (+res). A,B fp16; out fp32 C or fp16 Ch.
// 128x128 CTA tile, 8 warps, K-chunk 32 halves. smem stride 20 uint32/row.
// ============================================================================
#define STRH 20
#define STG_U32 (128 * STRH)            // uint32 per matrix per stage
#define GEMM_SMEM (4 * 2 * STG_U32 * 4) // 4 stages * (A+B) * 4 B = 81920

__global__ __launch_bounds__(256, 2) void gemm_h_kernel(
    const __half* __restrict__ A, const __half* __restrict__ B,
    const float* __restrict__ bias, const float* __restrict__ res,
    float* __restrict__ C, __half* __restrict__ Ch, int M, int N, int K)
{
    extern __shared__ uint32_t sm[];

    const int tid = threadIdx.x;
    const int wid = tid >> 5, lane = tid & 31;
    const int g = lane >> 2, qd = lane & 3;
    const int warpR = wid & 3, warpC = wid >> 2;
    const int m0 = blockIdx.y * 128, n0 = blockIdx.x * 128;

    const __half* Abase = A + (size_t)m0 * K;
    const __half* Bbase = B + (size_t)n0 * K;

    // loader: 2 threads per row; each thread 2x 16B chunks (16 halves)
    const int lr = tid >> 1;
    const int hsel = tid & 1;
    const size_t gsrc = (size_t)lr * K + hsel * 16;
    const uint32_t sbase = (uint32_t)__cvta_generic_to_shared(sm);
    const uint32_t dstoff = (uint32_t)(lr * STRH + hsel * 8) * 4;

    // ldmatrix lane-address components (byte offsets within a stage matrix)
    //  A x4 (mi): rows 0-15 klo (lanes 0-15), rows 0-15 khi (lanes 16-31)
    const uint32_t a_lane_off =
        (uint32_t)((warpR * 32 + (lane & 15)) * STRH + (lane >> 4) * 4) * 4;
    //  B x4 (njpair): rows {0-7 klo, 0-7 khi, 8-15 klo, 8-15 khi}
    const uint32_t b_lane_off =
        (uint32_t)((warpC * 64 + (lane >> 4) * 8 + (lane & 7)) * STRH +
                   ((lane >> 3) & 1) * 4) * 4;

    float acc[2][8][4];
    #pragma unroll
    for (int mi = 0; mi < 2; mi++)
        #pragma unroll
        for (int nj = 0; nj < 8; nj++)
            #pragma unroll
            for (int e = 0; e < 4; e++) acc[mi][nj][e] = 0.f;

    const int nk = K >> 5;  // K / 32

    // prologue: stages 0..2
    #pragma unroll
    for (int p = 0; p < 3; p++) {
        const uint32_t sa = sbase + (uint32_t)(2 * p) * (STG_U32 * 4) + dstoff;
        const uint32_t sb = sa + STG_U32 * 4;
        const int k0 = p * 32;
        cpa16(sa,      Abase + gsrc + k0);
        cpa16(sa + 16, Abase + gsrc + k0 + 8);
        cpa16(sb,      Bbase + gsrc + k0);
        cpa16(sb + 16, Bbase + gsrc + k0 + 8);
        CPA_COMMIT();
    }

    for (int kt = 0; kt < nk; kt++) {
        CPA_WAIT2();
        __syncthreads();

        const uint32_t sA = sbase + (uint32_t)(2 * (kt & 3)) * (STG_U32 * 4);
        const uint32_t sB = sA + STG_U32 * 4;
        #pragma unroll
        for (int ks = 0; ks < 2; ks++) {
            const uint32_t kso = (uint32_t)(ks * 8) * 4;
            uint32_t af[2][4];
            ldsm_x4(af[0][0], af[0][1], af[0][2], af[0][3],
                    sA + a_lane_off + kso);
            ldsm_x4(af[1][0], af[1][1], af[1][2], af[1][3],
                    sA + a_lane_off + kso + (uint32_t)(16 * STRH) * 4);
            #pragma unroll
            for (int np = 0; np < 4; np++) {
                uint32_t b0, b1, b2, b3;
                ldsm_x4(b0, b1, b2, b3,
                        sB + b_lane_off + kso + (uint32_t)(np * 16 * STRH) * 4);
                mma_f16(acc[0][np * 2],     af[0], b0, b1);
                mma_f16(acc[1][np * 2],     af[1], b0, b1);
                mma_f16(acc[0][np * 2 + 1], af[0], b2, b3);
                mma_f16(acc[1][np * 2 + 1], af[1], b2, b3);
            }
        }

        if (kt + 3 < nk) {
            const int p = (kt + 3) & 3;
            const uint32_t sa = sbase + (uint32_t)(2 * p) * (STG_U32 * 4) + dstoff;
            const uint32_t sb = sa + STG_U32 * 4;
            const int k0 = (kt + 3) * 32;
            cpa16(sa,      Abase + gsrc + k0);
            cpa16(sa + 16, Abase + gsrc + k0 + 8);
            cpa16(sb,      Bbase + gsrc + k0);
            cpa16(sb + 16, Bbase + gsrc + k0 + 8);
        }
        CPA_COMMIT();
    }

    // epilogue
    #pragma unroll
    for (int mi = 0; mi < 2; mi++) {
        const int rowa = m0 + warpR * 32 + mi * 16 + g;
        #pragma unroll
        for (int nj = 0; nj < 8; nj++) {
            const int col = n0 + warpC * 64 + nj * 8 + 2 * qd;
            float2 v0 = make_float2(acc[mi][nj][0], acc[mi][nj][1]);
            float2 v1 = make_float2(acc[mi][nj][2], acc[mi][nj][3]);
            if (bias) {
                const float bx = bias[col], by = bias[col + 1];
                v0.x += bx; v0.y += by;
                v1.x += bx; v1.y += by;
            }
            if (res) {
                float2 r0 = *(const float2*)(res + (size_t)rowa * N + col);
                float2 r1 = *(const float2*)(res + (size_t)(rowa + 8) * N + col);
                v0.x += r0.x; v0.y += r0.y;
                v1.x += r1.x; v1.y += r1.y;
            }
            if (C) {
                *(float2*)(C + (size_t)rowa * N + col) = v0;
                *(float2*)(C + (size_t)(rowa + 8) * N + col) = v1;
            } else {
                __half2 h0 = __floats2half2_rn(v0.x, v0.y);
                __half2 h1 = __floats2half2_rn(v1.x, v1.y);
                *(__half2*)(Ch + (size_t)rowa * N + col) = h0;
                *(__half2*)(Ch + (size_t)(rowa + 8) * N + col) = h1;
            }
        }
    }
}

// ============================================================================
// Tensor-core flash attention (causal), tf32 MMA + fp32 softmax.
// fp16 qkv input, fp16 output. 256 threads, Br=128, Bc=64, D=64.
// ============================================================================
#define AST 68
#define VST 72
#define ATT_SMEM ((128 * AST + 2 * 64 * AST + 2 * 64 * VST) * 4)

__global__ __launch_bounds__(256) void attn_kernel(
    const __half* __restrict__ qkv, __half* __restrict__ out)
{
    extern __shared__ uint32_t sh[];
    uint32_t* Qs = sh;
    uint32_t* Ks0 = sh + 128 * AST;
    uint32_t* Ks1 = Ks0 + 64 * AST;
    uint32_t* Vs0 = Ks1 + 64 * AST;
    uint32_t* Vs1 = Vs0 + 64 * VST;

    const int tid = threadIdx.x;
    const int wid = tid >> 5, lane = tid & 31;
    const int g = lane >> 2, qd = lane & 3;
    const int qb = blockIdx.x;
    const int bh = blockIdx.y;
    const int b = bh >> 4, h = bh & 15;
    const int i0 = qb << 7;
    const size_t base = (size_t)b * NN * (3 * CC) + h * DD;

    const int e = qd & 1;
    const int srcA = (lane & ~3) | (qd >> 1);
    const int srcB = srcA + 2;

    #pragma unroll
    for (int l = 0; l < 8; l++) {
        const int idx = tid + l * 256;
        const int r = idx >> 4, c = (idx & 15) << 2;
        uint2 raw = *(const uint2*)(qkv + base + (size_t)(i0 + r) * (3 * CC) + c);
        float2 f0 = __half22float2(*(__half2*)&raw.x);
        float2 f1 = __half22float2(*(__half2*)&raw.y);
        uint4 t;
        t.x = f32_to_tf32(f0.x * 0.125f); t.y = f32_to_tf32(f0.y * 0.125f);
        t.z = f32_to_tf32(f1.x * 0.125f); t.w = f32_to_tf32(f1.y * 0.125f);
        *(uint4*)&Qs[r * AST + c] = t;
    }

    const int lr[4] = { tid >> 4, (tid + 256) >> 4, (tid + 512) >> 4, (tid + 768) >> 4 };
    const int lc = (tid & 15) << 2;

    #pragma unroll
    for (int l = 0; l < 4; l++) {
        const int c = lr[l];
        uint2 kraw = *(const uint2*)(qkv + base + CC + (size_t)c * (3 * CC) + lc);
        float2 f0 = __half22float2(*(__half2*)&kraw.x);
        float2 f1 = __half22float2(*(__half2*)&kraw.y);
        uint4 t;
        t.x = f32_to_tf32(f0.x); t.y = f32_to_tf32(f0.y);
        t.z = f32_to_tf32(f1.x); t.w = f32_to_tf32(f1.y);
        *(uint4*)&Ks0[c * AST + lc] = t;
        uint2 vraw = *(const uint2*)(qkv + base + 2 * CC + (size_t)c * (3 * CC) + lc);
        f0 = __half22float2(*(__half2*)&vraw.x);
        f1 = __half22float2(*(__half2*)&vraw.y);
        t.x = f32_to_tf32(f0.x); t.y = f32_to_tf32(f0.y);
        t.z = f32_to_tf32(f1.x); t.w = f32_to_tf32(f1.y);
        *(uint4*)&Vs0[c * VST + lc] = t;
    }
    __syncthreads();

    float o[8][4];
    #pragma unroll
    for (int nj = 0; nj < 8; nj++)
        #pragma unroll
        for (int ee = 0; ee < 4; ee++) o[nj][ee] = 0.f;
    float m0 = -1e30f, m1 = -1e30f, l0 = 0.f, l1 = 0.f;

    const int rb = (wid * 16 + g) * AST;
    const int row0 = i0 + wid * 16 + g;
    const int kbmax = 2 * qb + 1;

    for (int kb = 0; kb <= kbmax; kb++) {
        const uint32_t* Ksc = (kb & 1) ? Ks1 : Ks0;
        const uint32_t* Vsc = (kb & 1) ? Vs1 : Vs0;
        uint32_t* Ksn = (kb & 1) ? Ks0 : Ks1;
        uint32_t* Vsn = (kb & 1) ? Vs0 : Vs1;
        const int k0r = kb << 6;
        const bool pref = (kb < kbmax);

        uint2 kreg[4], vreg[4];
        if (pref) {
            const int nk0 = k0r + 64;
            #pragma unroll
            for (int l = 0; l < 4; l++) {
                kreg[l] = *(const uint2*)(qkv + base + CC + (size_t)(nk0 + lr[l]) * (3 * CC) + lc);
                vreg[l] = *(const uint2*)(qkv + base + 2 * CC + (size_t)(nk0 + lr[l]) * (3 * CC) + lc);
            }
        }

        float s[8][4];
        #pragma unroll
        for (int nj = 0; nj < 8; nj++)
            #pragma unroll
            for (int ee = 0; ee < 4; ee++) s[nj][ee] = 0.f;

        #pragma unroll
        for (int ks = 0; ks < 8; ks++) {
            const int kc0 = ks * 8 + qd;
            uint32_t af[4];
            af[0] = Qs[rb + kc0];
            af[1] = Qs[rb + 8 * AST + kc0];
            af[2] = Qs[rb + kc0 + 4];
            af[3] = Qs[rb + 8 * AST + kc0 + 4];
            #pragma unroll
            for (int nj = 0; nj < 8; nj++) {
                const int nb = (nj * 8 + g) * AST;
                mma_tf32(s[nj], af, Ksc[nb + kc0], Ksc[nb + kc0 + 4]);
            }
        }

        if (kb >= 2 * qb) {
            #pragma unroll
            for (int nj = 0; nj < 8; nj++) {
                const int col = k0r + nj * 8 + 2 * qd;
                if (col > row0)     s[nj][0] = -1e30f;
                if (col + 1 > row0) s[nj][1] = -1e30f;
                if (col > row0 + 8)     s[nj][2] = -1e30f;
                if (col + 1 > row0 + 8) s[nj][3] = -1e30f;
            }
        }

        float mx0 = -1e30f, mx1 = -1e30f;
        #pragma unroll
        for (int nj = 0; nj < 8; nj++) {
            mx0 = fmaxf(mx0, fmaxf(s[nj][0], s[nj][1]));
            mx1 = fmaxf(mx1, fmaxf(s[nj][2], s[nj][3]));
        }
        mx0 = fmaxf(mx0, __shfl_xor_sync(0xffffffffu, mx0, 1));
        mx0 = fmaxf(mx0, __shfl_xor_sync(0xffffffffu, mx0, 2));
        mx1 = fmaxf(mx1, __shfl_xor_sync(0xffffffffu, mx1, 1));
        mx1 = fmaxf(mx1, __shfl_xor_sync(0xffffffffu, mx1, 2));

        const float mn0 = fmaxf(m0, mx0), mn1 = fmaxf(m1, mx1);
        const float al0 = __expf(m0 - mn0), al1 = __expf(m1 - mn1);
        m0 = mn0; m1 = mn1;

        float rs0 = 0.f, rs1 = 0.f;
        #pragma unroll
        for (int nj = 0; nj < 8; nj++) {
            s[nj][0] = __expf(s[nj][0] - mn0); rs0 += s[nj][0];
            s[nj][1] = __expf(s[nj][1] - mn0); rs0 += s[nj][1];
            s[nj][2] = __expf(s[nj][2] - mn1); rs1 += s[nj][2];
            s[nj][3] = __expf(s[nj][3] - mn1); rs1 += s[nj][3];
        }
        rs0 += __shfl_xor_sync(0xffffffffu, rs0, 1);
        rs0 += __shfl_xor_sync(0xffffffffu, rs0, 2);
        rs1 += __shfl_xor_sync(0xffffffffu, rs1, 1);
        rs1 += __shfl_xor_sync(0xffffffffu, rs1, 2);
        l0 = l0 * al0 + rs0;
        l1 = l1 * al1 + rs1;

        #pragma unroll
        for (int nj = 0; nj < 8; nj++) {
            o[nj][0] *= al0; o[nj][1] *= al0;
            o[nj][2] *= al1; o[nj][3] *= al1;
        }

        #pragma unroll
        for (int ks = 0; ks < 8; ks++) {
            const float p0a = __shfl_sync(0xffffffffu, s[ks][0], srcA);
            const float p0b = __shfl_sync(0xffffffffu, s[ks][1], srcA);
            const float p1a = __shfl_sync(0xffffffffu, s[ks][2], srcA);
            const float p1b = __shfl_sync(0xffffffffu, s[ks][3], srcA);
            const float p2a = __shfl_sync(0xffffffffu, s[ks][0], srcB);
            const float p2b = __shfl_sync(0xffffffffu, s[ks][1], srcB);
            const float p3a = __shfl_sync(0xffffffffu, s[ks][2], srcB);
            const float p3b = __shfl_sync(0xffffffffu, s[ks][3], srcB);
            uint32_t af[4];
            af[0] = f32_to_tf32(e ? p0b : p0a);
            af[1] = f32_to_tf32(e ? p1b : p1a);
            af[2] = f32_to_tf32(e ? p2b : p2a);
            af[3] = f32_to_tf32(e ? p3b : p3a);
            const int kc0 = ks * 8 + qd;
            #pragma unroll
            for (int nj = 0; nj < 8; nj++) {
                mma_tf32(o[nj], af,
                         Vsc[kc0 * VST + nj * 8 + g],
                         Vsc[(kc0 + 4) * VST + nj * 8 + g]);
            }
        }

        if (pref) {
            #pragma unroll
            for (int l = 0; l < 4; l++) {
                const int c = lr[l];
                float2 f0 = __half22float2(*(__half2*)&kreg[l].x);
                float2 f1 = __half22float2(*(__half2*)&kreg[l].y);
                uint4 t;
                t.x = f32_to_tf32(f0.x); t.y = f32_to_tf32(f0.y);
                t.z = f32_to_tf32(f1.x); t.w = f32_to_tf32(f1.y);
                *(uint4*)&Ksn[c * AST + lc] = t;
                f0 = __half22float2(*(__half2*)&vreg[l].x);
                f1 = __half22float2(*(__half2*)&vreg[l].y);
                t.x = f32_to_tf32(f0.x); t.y = f32_to_tf32(f0.y);
                t.z = f32_to_tf32(f1.x); t.w = f32_to_tf32(f1.y);
                *(uint4*)&Vsn[c * VST + lc] = t;
            }
        }
        __syncthreads();
    }

    const float inv0 = 1.f / l0, inv1 = 1.f / l1;
    const int orow = b * NN + row0;
    #pragma unroll
    for (int nj = 0; nj < 8; nj++) {
        const int col = h * DD + nj * 8 + 2 * qd;
        __half2 h0 = __floats2half2_rn(o[nj][0] * inv0, o[nj][1] * inv0);
        __half2 h1 = __floats2half2_rn(o[nj][2] * inv1, o[nj][3] * inv1);
        *(__half2*)(out + (size_t)orow * CC + col) = h0;
        *(__half2*)(out + (size_t)(orow + 8) * CC + col) = h1;
    }
}

// ============================================================================
// SwiGLU gate from fused b13 buffer: out[i,j] = silu(b13[i,j]) * b13[i,j+FFD]
// ============================================================================
__global__ __launch_bounds__(256) void glu_kernel(
    const __half* __restrict__ b13, __half* __restrict__ outh)
{
    const size_t flat = ((size_t)blockIdx.x * 256 + threadIdx.x) * 4;
    const size_t row = flat >> 12;            // / FFD
    const size_t j = flat & (FFD - 1);
    const __half* pa = b13 + row * (2 * FFD) + j;
    uint2 ar = *(const uint2*)pa;
    uint2 cr = *(const uint2*)(pa + FFD);
    float2 a0 = __half22float2(*(__half2*)&ar.x);
    float2 a1 = __half22float2(*(__half2*)&ar.y);
    float2 c0 = __half22float2(*(__half2*)&cr.x);
    float2 c1 = __half22float2(*(__half2*)&cr.y);
    a0.x = a0.x * c0.x / (1.f + __expf(-a0.x));
    a0.y = a0.y * c0.y / (1.f + __expf(-a0.y));
    a1.x = a1.x * c1.x / (1.f + __expf(-a1.x));
    a1.y = a1.y * c1.y / (1.f + __expf(-a1.y));
    __half2 h0 = __floats2half2_rn(a0.x, a0.y);
    __half2 h1 = __floats2half2_rn(a1.x, a1.y);
    uint2 o;
    o.x = *(uint32_t*)&h0; o.y = *(uint32_t*)&h1;
    *(uint2*)(outh + row * FFD + j) = o;
}

// ============================================================================
// Launch
// ============================================================================
extern "C" void kernel_launch(void* const* d_in, const int* in_sizes, int n_in,
                              void* d_out, int out_size)
{
    const float* x      = (const float*)d_in[0];
    // d_in[1] = mask (causal tril, hardcoded in attn kernel)
    const float* qkv_w  = (const float*)d_in[2];
    const float* qkv_b  = (const float*)d_in[3];
    const float* proj_w = (const float*)d_in[4];
    const float* proj_b = (const float*)d_in[5];
    const float* ln1_g  = (const float*)d_in[6];
    const float* ln1_b  = (const float*)d_in[7];
    const float* ln2_g  = (const float*)d_in[8];
    const float* ln2_b  = (const float*)d_in[9];
    const float* w1     = (const float*)d_in[10];
    const float* w2     = (const float*)d_in[11];
    const float* w3     = (const float*)d_in[12];
    float* out = (float*)d_out;

    __half *qkvw_h, *projw_h, *w13_h, *w2_h;
    __half *hh, *qkvh, *attnh, *b13h, *b1h;
    float* x1;
    cudaGetSymbolAddress((void**)&qkvw_h, g_qkvw_h);
    cudaGetSymbolAddress((void**)&projw_h, g_projw_h);
    cudaGetSymbolAddress((void**)&w13_h, g_w13_h);
    cudaGetSymbolAddress((void**)&w2_h, g_w2_h);
    cudaGetSymbolAddress((void**)&hh,   g_h_h);
    cudaGetSymbolAddress((void**)&qkvh, g_qkv_h);
    cudaGetSymbolAddress((void**)&attnh, g_attn_h);
    cudaGetSymbolAddress((void**)&x1,   g_x1);
    cudaGetSymbolAddress((void**)&b13h, g_b13_h);
    cudaGetSymbolAddress((void**)&b1h,  g_b1_h);

    cudaFuncSetAttribute(attn_kernel,
                         cudaFuncAttributeMaxDynamicSharedMemorySize, ATT_SMEM);
    cudaFuncSetAttribute(gemm_h_kernel,
                         cudaFuncAttributeMaxDynamicSharedMemorySize, GEMM_SMEM);

    // 0. weights -> fp16  (w1, w3 stacked into w13)
    f2h_kernel<<<(3 * CC * CC) / 1024, 256>>>(qkv_w, qkvw_h);
    f2h_kernel<<<(CC * CC) / 1024, 256>>>(proj_w, projw_h);
    f2h_kernel<<<(FFD * CC) / 1024, 256>>>(w1, w13_h);
    f2h_kernel<<<(FFD * CC) / 1024, 256>>>(w3, w13_h + (size_t)FFD * CC);
    f2h_kernel<<<(CC * FFD) / 1024, 256>>>(w2, w2_h);

    // 1. LN1 (fp16 out)
    ln_kernel<<<MROWS, 256>>>(x, ln1_g, ln1_b, hh);
    // 2. qkv = h @ qkv_w^T + qkv_b -> fp16   [8192, 3072]
    gemm_h_kernel<<<dim3(3 * CC / 128, MROWS / 128), 256, GEMM_SMEM>>>(
        hh, qkvw_h, qkv_b, nullptr, nullptr, qkvh, MROWS, 3 * CC, CC);
    // 3. causal flash attention -> fp16
    attn_kernel<<<dim3(NN / 128, BB * HH), 256, ATT_SMEM>>>(qkvh, attnh);
    // 4. x1 = x + attn @ proj_w^T + proj_b -> fp32
    gemm_h_kernel<<<dim3(CC / 128, MROWS / 128), 256, GEMM_SMEM>>>(
        attnh, projw_h, proj_b, x, x1, nullptr, MROWS, CC, CC);
    // 5. LN2 (fp16 out)
    ln_kernel<<<MROWS, 256>>>(x1, ln2_g, ln2_b, hh);
    // 6. b13 = h @ [w1;w3]^T -> fp16         [8192, 8192]
    gemm_h_kernel<<<dim3(2 * FFD / 128, MROWS / 128), 256, GEMM_SMEM>>>(
        hh, w13_h, nullptr, nullptr, nullptr, b13h, MROWS, 2 * FFD, CC);
    // 7. b1 = silu(b13[:, :FFD]) * b13[:, FFD:]
    glu_kernel<<<(MROWS * FFD) / 1024, 256>>>(b13h, b1h);
    // 8. out = x1 + b1 @ w2^T -> fp32        [8192, 1024]
    gemm_h_kernel<<<dim3(CC / 128, MROWS / 128), 256, GEMM_SMEM>>>(
        b1h, w2_h, nullptr, x1, out, nullptr, MROWS, CC, FFD);
}